// round 1
// baseline (speedup 1.0000x reference)
#include <cuda_runtime.h>
#include <math.h>

#define BB 8
#define NN 1024
#define DIMM 512
#define HH 8
#define DH 64
#define NTOK (BB*NN)          // 8192
#define INNER (HH*DH)         // 512
#define SATT 65               // padded shared stride for attention tiles

// Scratch (allocation-free rule: __device__ globals)
__device__ float g_q[BB*HH*NN*DH];
__device__ float g_k[BB*HH*NN*DH];
__device__ float g_v[BB*HH*NN*DH];
__device__ float g_att[(size_t)NTOK*INNER];

// ---------------------------------------------------------------------------
// Kernel 1: qkv = x @ w_qkv + b_qkv, fused SE(3) pose transform, scatter to
// head-major q/k/v buffers. Tile 64x64, K-chunk 16, 256 threads, 4x4/thread.
// Each thread's 4 contiguous output columns form exactly one SE(3) group.
// ---------------------------------------------------------------------------
__global__ __launch_bounds__(256) void qkv_pose_kernel(
    const float* __restrict__ x, const float* __restrict__ w,
    const float* __restrict__ bias, const float* __restrict__ rot,
    const float* __restrict__ tr)
{
    const int NT = 3 * INNER;  // 1536
    __shared__ float As[16][68];
    __shared__ __align__(16) float Bs[16][72];
    int t = threadIdx.x;
    int ty = t >> 4, tx = t & 15;
    int m0 = blockIdx.y << 6;
    int n0 = blockIdx.x << 6;

    float acc[4][4] = {};
    for (int k0 = 0; k0 < DIMM; k0 += 16) {
        int arow = t >> 2, ac4 = t & 3;
        float4 av = *(const float4*)(x + (size_t)(m0 + arow) * DIMM + k0 + ac4 * 4);
        As[ac4*4+0][arow] = av.x; As[ac4*4+1][arow] = av.y;
        As[ac4*4+2][arow] = av.z; As[ac4*4+3][arow] = av.w;
        int brow = t >> 4, bc4 = t & 15;
        float4 bv = *(const float4*)(w + (size_t)(k0 + brow) * NT + n0 + bc4 * 4);
        *(float4*)&Bs[brow][bc4*4] = bv;
        __syncthreads();
        #pragma unroll
        for (int kk = 0; kk < 16; kk++) {
            float a[4], bfr[4];
            #pragma unroll
            for (int i = 0; i < 4; i++) a[i] = As[kk][ty*4+i];
            #pragma unroll
            for (int j = 0; j < 4; j++) bfr[j] = Bs[kk][tx*4+j];
            #pragma unroll
            for (int i = 0; i < 4; i++)
                #pragma unroll
                for (int j = 0; j < 4; j++) acc[i][j] += a[i] * bfr[j];
        }
        __syncthreads();
    }

    int c = n0 + tx * 4;           // global output column; cols c..c+3 = one group
    int which = c >> 9;            // 0=q, 1=k, 2=v
    int h = (c & 511) >> 6;
    int d = c & 63;
    float* dstbuf = (which == 0) ? g_q : (which == 1 ? g_k : g_v);
    float b0 = bias[c+0], b1 = bias[c+1], b2 = bias[c+2], b3 = bias[c+3];

    #pragma unroll
    for (int i = 0; i < 4; i++) {
        int token = m0 + ty * 4 + i;
        int b = token >> 10, n = token & (NN - 1);
        const float* R = rot + (size_t)token * 9;
        const float* T = tr + (size_t)token * 3;
        float v0 = acc[i][0] + b0;
        float v1 = acc[i][1] + b1;
        float v2 = acc[i][2] + b2;
        float v3 = acc[i][3] + b3;
        float R00=R[0],R01=R[1],R02=R[2],R10=R[3],R11=R[4],R12=R[5],R20=R[6],R21=R[7],R22=R[8];
        float T0=T[0],T1=T[1],T2=T[2];
        // rotate first-3 of group by R
        float y0 = R00*v0 + R01*v1 + R02*v2;
        float y1 = R10*v0 + R11*v1 + R12*v2;
        float y2 = R20*v0 + R21*v1 + R22*v2;
        float y3;
        if (which == 0) {
            // q: P_qinv^T  => y = R v ; y3 = v3 - dot(t, R v)
            y3 = v3 - (T0*y0 + T1*y1 + T2*y2);
        } else {
            // k,v: P_kv => y = R v + t*v3 ; y3 = v3
            y0 += T0 * v3; y1 += T1 * v3; y2 += T2 * v3;
            y3 = v3;
        }
        size_t base = ((size_t)(b * HH + h) * NN + n) * DH + d;
        dstbuf[base+0] = y0; dstbuf[base+1] = y1;
        dstbuf[base+2] = y2; dstbuf[base+3] = y3;
    }
}

// ---------------------------------------------------------------------------
// Kernel 2: flash attention per (bh, 64-query tile). 64-key chunks, online
// softmax, 4x4 register microtiles for scores and PV. Epilogue fuses the
// inverse pose transform and relayout to token-major [B,N,INNER].
// ---------------------------------------------------------------------------
__global__ __launch_bounds__(256) void attn_kernel(
    const float* __restrict__ rot, const float* __restrict__ tr)
{
    extern __shared__ float sm[];
    float* qs = sm;                       // 64 x SATT
    float* ks = qs + 64 * SATT;
    float* vs = ks + 64 * SATT;
    float* ss = vs + 64 * SATT;
    float* alpha_sh = ss + 64 * SATT;     // 64
    float* rinv_sh  = alpha_sh + 64;      // 64

    int t = threadIdx.x;
    int bh = blockIdx.y;
    int q0 = blockIdx.x << 6;
    const float* qptr  = g_q + ((size_t)bh * NN + q0) * DH;
    const float* kbase = g_k + (size_t)bh * NN * DH;
    const float* vbase = g_v + (size_t)bh * NN * DH;

    for (int idx = t; idx < 4096; idx += 256)
        qs[(idx >> 6) * SATT + (idx & 63)] = qptr[idx];

    int qg = t >> 4, kg = t & 15;   // score & AV mapping (dg == kg)
    int qq = t >> 2, sub = t & 3;   // softmax mapping

    float acc[4][4] = {};
    float run_max = -1e30f, run_sum = 0.f;
    const float scale = 0.125f;     // DH^-0.5

    for (int kc = 0; kc < NN; kc += 64) {
        const float* kp = kbase + (size_t)kc * DH;
        const float* vp = vbase + (size_t)kc * DH;
        for (int idx = t; idx < 4096; idx += 256) {
            int r = idx >> 6, cl = idx & 63;
            ks[r * SATT + cl] = kp[idx];
            vs[r * SATT + cl] = vp[idx];
        }
        __syncthreads();

        // scores: 4 queries x 4 keys per thread
        float s[4][4] = {};
        #pragma unroll 4
        for (int dd = 0; dd < 64; dd++) {
            float qv[4], kv[4];
            #pragma unroll
            for (int i = 0; i < 4; i++) qv[i] = qs[(qg*4+i)*SATT + dd];
            #pragma unroll
            for (int j = 0; j < 4; j++) kv[j] = ks[(kg*4+j)*SATT + dd];
            #pragma unroll
            for (int i = 0; i < 4; i++)
                #pragma unroll
                for (int j = 0; j < 4; j++) s[i][j] += qv[i] * kv[j];
        }
        #pragma unroll
        for (int i = 0; i < 4; i++)
            #pragma unroll
            for (int j = 0; j < 4; j++)
                ss[(qg*4+i)*SATT + kg*4 + j] = s[i][j] * scale;
        __syncthreads();

        // online softmax: 4 lanes per query, 16 keys each
        float vals[16];
        float mloc = -1e30f;
        #pragma unroll
        for (int i = 0; i < 16; i++) {
            vals[i] = ss[qq*SATT + sub*16 + i];
            mloc = fmaxf(mloc, vals[i]);
        }
        mloc = fmaxf(mloc, __shfl_xor_sync(0xffffffffu, mloc, 1));
        mloc = fmaxf(mloc, __shfl_xor_sync(0xffffffffu, mloc, 2));
        float nmax = fmaxf(run_max, mloc);
        float al = __expf(run_max - nmax);
        float psum = 0.f;
        #pragma unroll
        for (int i = 0; i < 16; i++) {
            float p = __expf(vals[i] - nmax);
            psum += p;
            ss[qq*SATT + sub*16 + i] = p;
        }
        psum += __shfl_xor_sync(0xffffffffu, psum, 1);
        psum += __shfl_xor_sync(0xffffffffu, psum, 2);
        run_sum = run_sum * al + psum;
        run_max = nmax;
        if (sub == 0) alpha_sh[qq] = al;
        __syncthreads();

        // PV accumulate: 4 queries x 4 dims per thread
        float alv[4];
        #pragma unroll
        for (int i = 0; i < 4; i++) alv[i] = alpha_sh[qg*4+i];
        #pragma unroll
        for (int i = 0; i < 4; i++)
            #pragma unroll
            for (int j = 0; j < 4; j++) acc[i][j] *= alv[i];
        #pragma unroll 2
        for (int k = 0; k < 64; k++) {
            float p[4], vv[4];
            #pragma unroll
            for (int i = 0; i < 4; i++) p[i] = ss[(qg*4+i)*SATT + k];
            #pragma unroll
            for (int j = 0; j < 4; j++) vv[j] = vs[k*SATT + kg*4 + j];
            #pragma unroll
            for (int i = 0; i < 4; i++)
                #pragma unroll
                for (int j = 0; j < 4; j++) acc[i][j] += p[i] * vv[j];
        }
        __syncthreads();
    }

    if (sub == 0) rinv_sh[qq] = 1.f / run_sum;
    __syncthreads();

    // epilogue: normalize + inverse pose transform + relayout
    int b = bh >> 3, h = bh & 7;
    int dg = kg;   // dims dg*4..dg*4+3 = one SE(3) group
    #pragma unroll
    for (int i = 0; i < 4; i++) {
        int nq = q0 + qg*4 + i;
        int token = b * NN + nq;
        float inv = rinv_sh[qg*4+i];
        float v0 = acc[i][0]*inv, v1 = acc[i][1]*inv;
        float v2 = acc[i][2]*inv, v3 = acc[i][3]*inv;
        const float* R = rot + (size_t)token * 9;
        const float* T = tr + (size_t)token * 3;
        // y = R^T (v_{0:3} - t*v3); y3 = v3
        float x0 = v0 - T[0]*v3, x1 = v1 - T[1]*v3, x2 = v2 - T[2]*v3;
        float y0 = R[0]*x0 + R[3]*x1 + R[6]*x2;
        float y1 = R[1]*x0 + R[4]*x1 + R[7]*x2;
        float y2 = R[2]*x0 + R[5]*x1 + R[8]*x2;
        size_t o = (size_t)token * INNER + h * DH + dg * 4;
        g_att[o+0] = y0; g_att[o+1] = y1; g_att[o+2] = y2; g_att[o+3] = v3;
    }
}

// ---------------------------------------------------------------------------
// Kernel 3: out = g_att @ w_out + b_out. Same tiling as kernel 1.
// ---------------------------------------------------------------------------
__global__ __launch_bounds__(256) void out_kernel(
    const float* __restrict__ w, const float* __restrict__ bias,
    float* __restrict__ out)
{
    const int NT = DIMM;  // 512
    __shared__ float As[16][68];
    __shared__ __align__(16) float Bs[16][72];
    int t = threadIdx.x;
    int ty = t >> 4, tx = t & 15;
    int m0 = blockIdx.y << 6;
    int n0 = blockIdx.x << 6;

    float acc[4][4] = {};
    for (int k0 = 0; k0 < INNER; k0 += 16) {
        int arow = t >> 2, ac4 = t & 3;
        float4 av = *(const float4*)(g_att + (size_t)(m0 + arow) * INNER + k0 + ac4 * 4);
        As[ac4*4+0][arow] = av.x; As[ac4*4+1][arow] = av.y;
        As[ac4*4+2][arow] = av.z; As[ac4*4+3][arow] = av.w;
        int brow = t >> 4, bc4 = t & 15;
        float4 bv = *(const float4*)(w + (size_t)(k0 + brow) * NT + n0 + bc4 * 4);
        *(float4*)&Bs[brow][bc4*4] = bv;
        __syncthreads();
        #pragma unroll
        for (int kk = 0; kk < 16; kk++) {
            float a[4], bfr[4];
            #pragma unroll
            for (int i = 0; i < 4; i++) a[i] = As[kk][ty*4+i];
            #pragma unroll
            for (int j = 0; j < 4; j++) bfr[j] = Bs[kk][tx*4+j];
            #pragma unroll
            for (int i = 0; i < 4; i++)
                #pragma unroll
                for (int j = 0; j < 4; j++) acc[i][j] += a[i] * bfr[j];
        }
        __syncthreads();
    }

    int c = n0 + tx * 4;
    float b0 = bias[c+0], b1 = bias[c+1], b2 = bias[c+2], b3 = bias[c+3];
    #pragma unroll
    for (int i = 0; i < 4; i++) {
        int m = m0 + ty * 4 + i;
        float4 o;
        o.x = acc[i][0] + b0; o.y = acc[i][1] + b1;
        o.z = acc[i][2] + b2; o.w = acc[i][3] + b3;
        *(float4*)(out + (size_t)m * NT + c) = o;
    }
}

// ---------------------------------------------------------------------------
extern "C" void kernel_launch(void* const* d_in, const int* in_sizes, int n_in,
                              void* d_out, int out_size)
{
    const float* x     = (const float*)d_in[0];
    const float* rot   = (const float*)d_in[1];
    const float* tr    = (const float*)d_in[2];
    const float* w_qkv = (const float*)d_in[3];
    const float* b_qkv = (const float*)d_in[4];
    const float* w_out = (const float*)d_in[5];
    const float* b_out = (const float*)d_in[6];
    float* out = (float*)d_out;

    // QKV GEMM + pose: grid = (1536/64 N-tiles, 8192/64 M-tiles)
    qkv_pose_kernel<<<dim3(24, 128), 256>>>(x, w_qkv, b_qkv, rot, tr);

    // Attention: grid = (1024/64 q-tiles, B*H)
    size_t shmem = (size_t)(4 * 64 * SATT + 128) * sizeof(float);  // 67072 B
    cudaFuncSetAttribute(attn_kernel, cudaFuncAttributeMaxDynamicSharedMemorySize,
                         (int)shmem);
    attn_kernel<<<dim3(16, 64), 256, shmem>>>(rot, tr);

    // Output GEMM: grid = (512/64, 8192/64)
    out_kernel<<<dim3(8, 128), 256>>>(w_out, b_out, out);
}

// round 2
// speedup vs baseline: 1.2416x; 1.2416x over previous
#include <cuda_runtime.h>
#include <math.h>

#define BB 8
#define NN 1024
#define DIMM 512
#define HH 8
#define DH 64
#define NTOK (BB*NN)          // 8192
#define INNER (HH*DH)         // 512

// Scratch (allocation-free rule: __device__ globals)
__device__ float g_q[BB*HH*NN*DH];
__device__ float g_k[BB*HH*NN*DH];
__device__ float g_v[BB*HH*NN*DH];
__device__ float g_att[(size_t)NTOK*INNER];

// ---------------------------------------------------------------------------
// Kernel 1: qkv = x @ w_qkv + b_qkv, fused SE(3) pose, scatter to head-major
// q/k/v. 128x128 tile, K-chunk 16, 256 threads, 8x8/thread, double-buffered.
// ---------------------------------------------------------------------------
__global__ __launch_bounds__(256, 2) void qkv_pose_kernel(
    const float* __restrict__ x, const float* __restrict__ w,
    const float* __restrict__ bias, const float* __restrict__ rot,
    const float* __restrict__ tr)
{
    const int NT = 3 * INNER;  // 1536
    __shared__ float As[2][16][132];   // As[buf][k][m]
    __shared__ float Bs[2][16][132];   // Bs[buf][k][n]
    int t  = threadIdx.x;
    int ty = t >> 4, tx = t & 15;
    int m0 = blockIdx.y << 7;
    int n0 = blockIdx.x << 7;

    int arow = t >> 1, ak = (t & 1) * 8;           // A: 128 rows x 16 k
    int brow = ty,     bcol = tx * 8;              // B: 16 rows x 128 cols
    const float* xg = x + (size_t)(m0 + arow) * DIMM + ak;
    const float* wg = w + (size_t)brow * NT + n0 + bcol;

    float4 a0 = *(const float4*)(xg);
    float4 a1 = *(const float4*)(xg + 4);
    float4 b0 = *(const float4*)(wg);
    float4 b1 = *(const float4*)(wg + 4);

    float acc[8][8] = {};
    int buf = 0;
    for (int k0 = 0; k0 < DIMM; k0 += 16) {
        As[buf][ak+0][arow]=a0.x; As[buf][ak+1][arow]=a0.y;
        As[buf][ak+2][arow]=a0.z; As[buf][ak+3][arow]=a0.w;
        As[buf][ak+4][arow]=a1.x; As[buf][ak+5][arow]=a1.y;
        As[buf][ak+6][arow]=a1.z; As[buf][ak+7][arow]=a1.w;
        *(float4*)&Bs[buf][brow][bcol]   = b0;
        *(float4*)&Bs[buf][brow][bcol+4] = b1;
        __syncthreads();
        if (k0 + 16 < DIMM) {
            a0 = *(const float4*)(xg + k0 + 16);
            a1 = *(const float4*)(xg + k0 + 20);
            b0 = *(const float4*)(wg + (size_t)(k0 + 16) * NT);
            b1 = *(const float4*)(wg + (size_t)(k0 + 16) * NT + 4);
        }
        #pragma unroll
        for (int kk = 0; kk < 16; kk++) {
            float a[8], bb[8];
            *(float4*)&a[0]  = *(const float4*)&As[buf][kk][ty*8];
            *(float4*)&a[4]  = *(const float4*)&As[buf][kk][ty*8+4];
            *(float4*)&bb[0] = *(const float4*)&Bs[buf][kk][tx*8];
            *(float4*)&bb[4] = *(const float4*)&Bs[buf][kk][tx*8+4];
            #pragma unroll
            for (int i = 0; i < 8; i++)
                #pragma unroll
                for (int j = 0; j < 8; j++) acc[i][j] += a[i] * bb[j];
        }
        buf ^= 1;
    }

    int c = n0 + tx * 8;           // 8 cols = 2 SE(3) groups, same which/head
    int which = c >> 9;            // 0=q, 1=k, 2=v
    int h = (c & 511) >> 6;
    int d = c & 63;
    float* dstbuf = (which == 0) ? g_q : (which == 1 ? g_k : g_v);
    float bv[8];
    #pragma unroll
    for (int j = 0; j < 8; j++) bv[j] = bias[c+j];

    #pragma unroll
    for (int i = 0; i < 8; i++) {
        int token = m0 + ty * 8 + i;
        int b = token >> 10, n = token & (NN - 1);
        const float* R = rot + (size_t)token * 9;
        const float* T = tr + (size_t)token * 3;
        float R00=R[0],R01=R[1],R02=R[2],R10=R[3],R11=R[4],R12=R[5],R20=R[6],R21=R[7],R22=R[8];
        float T0=T[0],T1=T[1],T2=T[2];
        size_t base = ((size_t)(b * HH + h) * NN + n) * DH + d;
        #pragma unroll
        for (int g = 0; g < 2; g++) {
            float v0 = acc[i][g*4+0] + bv[g*4+0];
            float v1 = acc[i][g*4+1] + bv[g*4+1];
            float v2 = acc[i][g*4+2] + bv[g*4+2];
            float v3 = acc[i][g*4+3] + bv[g*4+3];
            float y0 = R00*v0 + R01*v1 + R02*v2;
            float y1 = R10*v0 + R11*v1 + R12*v2;
            float y2 = R20*v0 + R21*v1 + R22*v2;
            float y3;
            if (which == 0) {
                y3 = v3 - (T0*y0 + T1*y1 + T2*y2);
            } else {
                y0 += T0 * v3; y1 += T1 * v3; y2 += T2 * v3;
                y3 = v3;
            }
            float4 o; o.x=y0; o.y=y1; o.z=y2; o.w=y3;
            *(float4*)(dstbuf + base + g*4) = o;
        }
    }
}

// ---------------------------------------------------------------------------
// Kernel 2: flash attention, 128 queries/block, 64-key chunks, 8x4/thread.
// Shared layouts tuned: q reads broadcast, k reads 2-way, ss/vs float4.
// Epilogue fuses inverse pose transform + relayout.
// ---------------------------------------------------------------------------
#define SQ 68
#define SKK 65
#define SV 68
#define SS 68

__global__ __launch_bounds__(256, 2) void attn_kernel(
    const float* __restrict__ rot, const float* __restrict__ tr)
{
    extern __shared__ float sm[];
    float* qs = sm;                       // [128][SQ]
    float* ks = qs + 128 * SQ;            // [64][SKK]
    float* vs = ks + 64 * SKK;            // [64][SV]
    float* ss = vs + 64 * SV;             // [128][SS]
    float* alpha_sh = ss + 128 * SS;      // [128]
    float* rinv_sh  = alpha_sh + 128;     // [128]

    int t = threadIdx.x;
    int bh = blockIdx.y;
    int q0 = blockIdx.x << 7;
    const float* qptr  = g_q + ((size_t)bh * NN + q0) * DH;
    const float* kbase = g_k + (size_t)bh * NN * DH;
    const float* vbase = g_v + (size_t)bh * NN * DH;

    const float scale = 0.125f;   // folded into q
    // load q tile (128 x 64), scale folded
    for (int i = t; i < 2048; i += 256) {
        float4 v = *(const float4*)(qptr + (size_t)i * 4);
        int n = i >> 4, d0 = (i & 15) * 4;
        float4 o; o.x=v.x*scale; o.y=v.y*scale; o.z=v.z*scale; o.w=v.w*scale;
        *(float4*)&qs[n*SQ + d0] = o;
    }

    int qg = t >> 4, kg = t & 15;   // score & PV mapping
    int qq = t >> 1, sub = t & 1;   // softmax mapping (2 thr/query, 32 k each)

    float acc[8][4] = {};
    float run_max = -1e30f, run_sum = 0.f;

    for (int kc = 0; kc < NN; kc += 64) {
        const float* kp = kbase + (size_t)kc * DH;
        const float* vp = vbase + (size_t)kc * DH;
        for (int i = t; i < 1024; i += 256) {
            float4 kv4 = *(const float4*)(kp + (size_t)i * 4);
            float4 vv4 = *(const float4*)(vp + (size_t)i * 4);
            int n = i >> 4, d0 = (i & 15) * 4;
            ks[n*SKK + d0+0]=kv4.x; ks[n*SKK + d0+1]=kv4.y;
            ks[n*SKK + d0+2]=kv4.z; ks[n*SKK + d0+3]=kv4.w;
            *(float4*)&vs[n*SV + d0] = vv4;
        }
        __syncthreads();

        // scores: 8 queries x 4 keys per thread
        float s[8][4] = {};
        #pragma unroll 8
        for (int dd = 0; dd < 64; dd++) {
            float qv[8], kv[4];
            #pragma unroll
            for (int i = 0; i < 8; i++) qv[i] = qs[(qg*8+i)*SQ + dd];
            #pragma unroll
            for (int j = 0; j < 4; j++) kv[j] = ks[(kg*4+j)*SKK + dd];
            #pragma unroll
            for (int i = 0; i < 8; i++)
                #pragma unroll
                for (int j = 0; j < 4; j++) s[i][j] += qv[i] * kv[j];
        }
        #pragma unroll
        for (int i = 0; i < 8; i++) {
            float4 o; o.x=s[i][0]; o.y=s[i][1]; o.z=s[i][2]; o.w=s[i][3];
            *(float4*)&ss[(qg*8+i)*SS + kg*4] = o;
        }
        __syncthreads();

        // online softmax
        float* row = ss + qq*SS + sub*32;
        float mloc = -1e30f;
        #pragma unroll
        for (int i4 = 0; i4 < 8; i4++) {
            float4 v = *(const float4*)&row[i4*4];
            mloc = fmaxf(mloc, fmaxf(fmaxf(v.x, v.y), fmaxf(v.z, v.w)));
        }
        mloc = fmaxf(mloc, __shfl_xor_sync(0xffffffffu, mloc, 1));
        float nmax = fmaxf(run_max, mloc);
        float al = __expf(run_max - nmax);
        float psum = 0.f;
        #pragma unroll
        for (int i4 = 0; i4 < 8; i4++) {
            float4 v = *(const float4*)&row[i4*4];
            v.x = __expf(v.x - nmax); v.y = __expf(v.y - nmax);
            v.z = __expf(v.z - nmax); v.w = __expf(v.w - nmax);
            psum += v.x + v.y + v.z + v.w;
            *(float4*)&row[i4*4] = v;
        }
        psum += __shfl_xor_sync(0xffffffffu, psum, 1);
        run_sum = run_sum * al + psum;
        run_max = nmax;
        if (sub == 0) alpha_sh[qq] = al;
        __syncthreads();

        // PV accumulate: 8 queries x 4 dims per thread
        float alv[8];
        #pragma unroll
        for (int i = 0; i < 8; i++) alv[i] = alpha_sh[qg*8+i];
        #pragma unroll
        for (int i = 0; i < 8; i++)
            #pragma unroll
            for (int j = 0; j < 4; j++) acc[i][j] *= alv[i];
        #pragma unroll 4
        for (int k = 0; k < 64; k++) {
            float p[8];
            #pragma unroll
            for (int i = 0; i < 8; i++) p[i] = ss[(qg*8+i)*SS + k];
            float4 vv = *(const float4*)&vs[k*SV + kg*4];
            #pragma unroll
            for (int i = 0; i < 8; i++) {
                acc[i][0] += p[i] * vv.x;
                acc[i][1] += p[i] * vv.y;
                acc[i][2] += p[i] * vv.z;
                acc[i][3] += p[i] * vv.w;
            }
        }
        __syncthreads();
    }

    if (sub == 0) rinv_sh[qq] = 1.f / run_sum;
    __syncthreads();

    // epilogue: normalize + inverse pose transform + relayout
    int b = bh >> 3, h = bh & 7;
    #pragma unroll
    for (int i = 0; i < 8; i++) {
        int nq = q0 + qg*8 + i;
        int token = b * NN + nq;
        float inv = rinv_sh[qg*8+i];
        float v0 = acc[i][0]*inv, v1 = acc[i][1]*inv;
        float v2 = acc[i][2]*inv, v3 = acc[i][3]*inv;
        const float* R = rot + (size_t)token * 9;
        const float* T = tr + (size_t)token * 3;
        float x0 = v0 - T[0]*v3, x1 = v1 - T[1]*v3, x2 = v2 - T[2]*v3;
        float y0 = R[0]*x0 + R[3]*x1 + R[6]*x2;
        float y1 = R[1]*x0 + R[4]*x1 + R[7]*x2;
        float y2 = R[2]*x0 + R[5]*x1 + R[8]*x2;
        float4 o; o.x=y0; o.y=y1; o.z=y2; o.w=v3;
        *(float4*)(g_att + (size_t)token * INNER + h * DH + kg * 4) = o;
    }
}

// ---------------------------------------------------------------------------
// Kernel 3: out = g_att @ w_out + b_out. 128x128 tile, 8x8, double-buffered.
// ---------------------------------------------------------------------------
__global__ __launch_bounds__(256, 2) void out_kernel(
    const float* __restrict__ w, const float* __restrict__ bias,
    float* __restrict__ out)
{
    const int NT = DIMM;  // 512
    __shared__ float As[2][16][132];
    __shared__ float Bs[2][16][132];
    int t  = threadIdx.x;
    int ty = t >> 4, tx = t & 15;
    int m0 = blockIdx.y << 7;
    int n0 = blockIdx.x << 7;

    int arow = t >> 1, ak = (t & 1) * 8;
    int brow = ty,     bcol = tx * 8;
    const float* ag = g_att + (size_t)(m0 + arow) * INNER + ak;
    const float* wg = w + (size_t)brow * NT + n0 + bcol;

    float4 a0 = *(const float4*)(ag);
    float4 a1 = *(const float4*)(ag + 4);
    float4 b0 = *(const float4*)(wg);
    float4 b1 = *(const float4*)(wg + 4);

    float acc[8][8] = {};
    int buf = 0;
    for (int k0 = 0; k0 < INNER; k0 += 16) {
        As[buf][ak+0][arow]=a0.x; As[buf][ak+1][arow]=a0.y;
        As[buf][ak+2][arow]=a0.z; As[buf][ak+3][arow]=a0.w;
        As[buf][ak+4][arow]=a1.x; As[buf][ak+5][arow]=a1.y;
        As[buf][ak+6][arow]=a1.z; As[buf][ak+7][arow]=a1.w;
        *(float4*)&Bs[buf][brow][bcol]   = b0;
        *(float4*)&Bs[buf][brow][bcol+4] = b1;
        __syncthreads();
        if (k0 + 16 < INNER) {
            a0 = *(const float4*)(ag + k0 + 16);
            a1 = *(const float4*)(ag + k0 + 20);
            b0 = *(const float4*)(wg + (size_t)(k0 + 16) * NT);
            b1 = *(const float4*)(wg + (size_t)(k0 + 16) * NT + 4);
        }
        #pragma unroll
        for (int kk = 0; kk < 16; kk++) {
            float a[8], bb[8];
            *(float4*)&a[0]  = *(const float4*)&As[buf][kk][ty*8];
            *(float4*)&a[4]  = *(const float4*)&As[buf][kk][ty*8+4];
            *(float4*)&bb[0] = *(const float4*)&Bs[buf][kk][tx*8];
            *(float4*)&bb[4] = *(const float4*)&Bs[buf][kk][tx*8+4];
            #pragma unroll
            for (int i = 0; i < 8; i++)
                #pragma unroll
                for (int j = 0; j < 8; j++) acc[i][j] += a[i] * bb[j];
        }
        buf ^= 1;
    }

    int c = n0 + tx * 8;
    float bv[8];
    #pragma unroll
    for (int j = 0; j < 8; j++) bv[j] = bias[c+j];
    #pragma unroll
    for (int i = 0; i < 8; i++) {
        int m = m0 + ty * 8 + i;
        float4 o0, o1;
        o0.x = acc[i][0] + bv[0]; o0.y = acc[i][1] + bv[1];
        o0.z = acc[i][2] + bv[2]; o0.w = acc[i][3] + bv[3];
        o1.x = acc[i][4] + bv[4]; o1.y = acc[i][5] + bv[5];
        o1.z = acc[i][6] + bv[6]; o1.w = acc[i][7] + bv[7];
        *(float4*)(out + (size_t)m * NT + c)     = o0;
        *(float4*)(out + (size_t)m * NT + c + 4) = o1;
    }
}

// ---------------------------------------------------------------------------
extern "C" void kernel_launch(void* const* d_in, const int* in_sizes, int n_in,
                              void* d_out, int out_size)
{
    const float* x     = (const float*)d_in[0];
    const float* rot   = (const float*)d_in[1];
    const float* tr    = (const float*)d_in[2];
    const float* w_qkv = (const float*)d_in[3];
    const float* b_qkv = (const float*)d_in[4];
    const float* w_out = (const float*)d_in[5];
    const float* b_out = (const float*)d_in[6];
    float* out = (float*)d_out;

    // QKV GEMM + pose: grid = (1536/128, 8192/128)
    qkv_pose_kernel<<<dim3(12, 64), 256>>>(x, w_qkv, b_qkv, rot, tr);

    // Attention: grid = (1024/128 q-tiles, B*H)
    size_t shmem = (size_t)(128*SQ + 64*SKK + 64*SV + 128*SS + 256) * sizeof(float);
    cudaFuncSetAttribute(attn_kernel, cudaFuncAttributeMaxDynamicSharedMemorySize,
                         (int)shmem);
    attn_kernel<<<dim3(8, 64), 256, shmem>>>(rot, tr);

    // Output GEMM: grid = (512/128, 8192/128)
    out_kernel<<<dim3(4, 64), 256>>>(w_out, b_out, out);
}

// round 4
// speedup vs baseline: 1.6745x; 1.3486x over previous
#include <cuda_runtime.h>
#include <cuda_bf16.h>
#include <cstdint>
#include <math.h>

#define BB 8
#define NN 1024
#define DIMM 512
#define HH 8
#define DH 64
#define NTOK (BB*NN)          // 8192
#define INNER (HH*DH)         // 512

// Scratch (allocation-free rule: __device__ globals)
__device__ float g_q[BB*HH*NN*DH];
__device__ float g_k[BB*HH*NN*DH];
__device__ float g_v[BB*HH*NN*DH];
__device__ float g_att[(size_t)NTOK*INNER];
__device__ __nv_bfloat16 g_wqkvT_h[3*INNER*DIMM];
__device__ __nv_bfloat16 g_wqkvT_l[3*INNER*DIMM];
__device__ __nv_bfloat16 g_woutT_h[DIMM*INNER];
__device__ __nv_bfloat16 g_woutT_l[DIMM*INNER];

// ===================== helpers =====================
__device__ __forceinline__ uint32_t smem_to_u32(const void* p) {
    uint32_t a;
    asm("{ .reg .u64 t; cvta.to.shared.u64 t, %1; cvt.u32.u64 %0, t; }"
        : "=r"(a) : "l"(p));
    return a;
}
#define SW128(o) ((o) ^ (((o) >> 3) & 0x70))

__device__ __forceinline__ void ldmx4(uint32_t* r, uint32_t a) {
    asm volatile("ldmatrix.sync.aligned.m8n8.x4.shared.b16 {%0,%1,%2,%3}, [%4];"
        : "=r"(r[0]), "=r"(r[1]), "=r"(r[2]), "=r"(r[3]) : "r"(a));
}
__device__ __forceinline__ void mma16816(float* d, const uint32_t* a, const uint32_t* b) {
    asm volatile("mma.sync.aligned.m16n8k16.row.col.f32.bf16.bf16.f32 "
        "{%0,%1,%2,%3}, {%4,%5,%6,%7}, {%8,%9}, {%0,%1,%2,%3};"
        : "+f"(d[0]), "+f"(d[1]), "+f"(d[2]), "+f"(d[3])
        : "r"(a[0]), "r"(a[1]), "r"(a[2]), "r"(a[3]), "r"(b[0]), "r"(b[1]));
}
__device__ __forceinline__ void cp16(uint32_t dst, const void* src) {
    asm volatile("cp.async.cg.shared.global [%0], [%1], 16;" :: "r"(dst), "l"(src));
}
#define CP_COMMIT() asm volatile("cp.async.commit_group;" ::: "memory")
#define CP_WAIT0()  asm volatile("cp.async.wait_group 0;" ::: "memory")

__device__ __forceinline__ uint32_t pack_bf16(float lo, float hi) {
    uint32_t r;
    asm("cvt.rn.bf16x2.f32 %0, %1, %2;" : "=r"(r) : "f"(hi), "f"(lo));
    return r;
}

// ===================== transpose + bf16-split of W =====================
// src [K][N] fp32 -> dh/dl [N][K] bf16 (hi/lo split)
__global__ void transpose_split_kernel(const float* __restrict__ src,
                                       __nv_bfloat16* __restrict__ dh,
                                       __nv_bfloat16* __restrict__ dl,
                                       int K, int N)
{
    __shared__ float ts[32][33];
    int n0 = blockIdx.x << 5, k0 = blockIdx.y << 5;
    int tx = threadIdx.x, ty = threadIdx.y;
    #pragma unroll
    for (int i = 0; i < 32; i += 8)
        ts[ty + i][tx] = src[(size_t)(k0 + ty + i) * N + n0 + tx];
    __syncthreads();
    #pragma unroll
    for (int i = 0; i < 32; i += 8) {
        float v = ts[tx][ty + i];
        __nv_bfloat16 h = __float2bfloat16(v);
        float lo = v - __bfloat162float(h);
        size_t o = (size_t)(n0 + ty + i) * K + k0 + tx;
        dh[o] = h;
        dl[o] = __float2bfloat16(lo);
    }
}

// ===================== mma.sync bf16-split GEMM =====================
// C[M][Ntot] = A[M][512] (fp32, split in-kernel) @ B^T (B pre-split [Ntot][512])
// CTA tile 128x128, 8 warps of 64x32, K-chunk 64, double-buffered.
// mode 0: qkv (pose epilogue -> g_q/g_k/g_v), mode 1: out proj (bias -> outp)
__global__ __launch_bounds__(256, 1) void mma_gemm_kernel(
    const float* __restrict__ A,
    const __nv_bfloat16* __restrict__ Bh,
    const __nv_bfloat16* __restrict__ Bl,
    const float* __restrict__ bias,
    const float* __restrict__ rot, const float* __restrict__ tr,
    float* __restrict__ outp, int mode)
{
    extern __shared__ char smem[];
    uint32_t base = (smem_to_u32(smem) + 127) & ~127u;
    // per buffer: Ah 16K | Al 16K | Bh 16K | Bl 16K  (64KB); two buffers
    int t = threadIdx.x, lane = t & 31, w = t >> 5;
    int m0 = blockIdx.y << 7, n0 = blockIdx.x << 7;
    int mbase = (w >> 2) * 64, nbase = (w & 3) * 32;

    // loader indexing: 1024 16B-chunks per operand per chunk-iter; 4 per thread
    int rowc[4], k8c[4]; uint32_t swc[4];
    #pragma unroll
    for (int c = 0; c < 4; c++) {
        int ci = t + c * 256;
        rowc[c] = ci >> 3; k8c[c] = ci & 7;
        swc[c] = SW128((uint32_t)(rowc[c] * 128 + k8c[c] * 16));
    }

    float acc[4][4][4] = {};
    uint32_t pah[4][4], pal[4][4];   // A prefetch (converted bf16 hi/lo)

    // ---- load A chunk kc into regs ----
    #define LOAD_A_REGS(kc) do { \
        _Pragma("unroll") \
        for (int c = 0; c < 4; c++) { \
            const float* ap = A + (size_t)(m0 + rowc[c]) * 512 + (kc) * 64 + k8c[c] * 8; \
            float4 f0 = *(const float4*)ap; \
            float4 f1 = *(const float4*)(ap + 4); \
            uint32_t h0 = pack_bf16(f0.x, f0.y), h1 = pack_bf16(f0.z, f0.w); \
            uint32_t h2 = pack_bf16(f1.x, f1.y), h3 = pack_bf16(f1.z, f1.w); \
            float r0 = f0.x - __uint_as_float(h0 << 16); \
            float r1 = f0.y - __uint_as_float(h0 & 0xFFFF0000u); \
            float r2 = f0.z - __uint_as_float(h1 << 16); \
            float r3 = f0.w - __uint_as_float(h1 & 0xFFFF0000u); \
            float r4 = f1.x - __uint_as_float(h2 << 16); \
            float r5 = f1.y - __uint_as_float(h2 & 0xFFFF0000u); \
            float r6 = f1.z - __uint_as_float(h3 << 16); \
            float r7 = f1.w - __uint_as_float(h3 & 0xFFFF0000u); \
            pah[c][0] = h0; pah[c][1] = h1; pah[c][2] = h2; pah[c][3] = h3; \
            pal[c][0] = pack_bf16(r0, r1); pal[c][1] = pack_bf16(r2, r3); \
            pal[c][2] = pack_bf16(r4, r5); pal[c][3] = pack_bf16(r6, r7); \
        } \
    } while (0)

    #define STS_A(bb) do { \
        uint32_t bA = base + (bb) * 65536; \
        _Pragma("unroll") \
        for (int c = 0; c < 4; c++) { \
            uint4 hv = make_uint4(pah[c][0], pah[c][1], pah[c][2], pah[c][3]); \
            uint4 lv = make_uint4(pal[c][0], pal[c][1], pal[c][2], pal[c][3]); \
            *(uint4*)(smem + (bA + swc[c] - smem_to_u32(smem)))           = hv; \
            *(uint4*)(smem + (bA + 16384 + swc[c] - smem_to_u32(smem)))   = lv; \
        } \
    } while (0)

    #define LOAD_B_ASYNC(kc, bb) do { \
        uint32_t bB = base + (bb) * 65536 + 32768; \
        _Pragma("unroll") \
        for (int c = 0; c < 4; c++) { \
            const __nv_bfloat16* gh = Bh + (size_t)(n0 + rowc[c]) * 512 + (kc) * 64 + k8c[c] * 8; \
            const __nv_bfloat16* gl = Bl + (size_t)(n0 + rowc[c]) * 512 + (kc) * 64 + k8c[c] * 8; \
            cp16(bB + swc[c], gh); \
            cp16(bB + 16384 + swc[c], gl); \
        } \
        CP_COMMIT(); \
    } while (0)

    // ldmatrix per-lane address components
    int arow = lane & 15;
    int acolb = (lane >> 4) * 16;
    int bg = lane >> 3;
    int brow_in = lane & 7;

    // prologue: chunk 0
    LOAD_B_ASYNC(0, 0);
    LOAD_A_REGS(0);
    STS_A(0);
    CP_WAIT0();
    __syncthreads();

    int buf = 0;
    for (int kc = 0; kc < 8; kc++) {
        if (kc < 7) {
            LOAD_B_ASYNC(kc + 1, buf ^ 1);
            LOAD_A_REGS(kc + 1);
        }
        uint32_t AhS = base + buf * 65536;
        uint32_t AlS = AhS + 16384;
        uint32_t BhS = AhS + 32768;
        uint32_t BlS = AhS + 49152;
        #pragma unroll
        for (int ks = 0; ks < 4; ks++) {
            uint32_t ah[4][4], al[4][4], bh[4][2], bl[4][2];
            #pragma unroll
            for (int i = 0; i < 4; i++) {
                uint32_t off = SW128((uint32_t)((mbase + i*16 + arow) * 128 + ks*32 + acolb));
                ldmx4(ah[i], AhS + off);
                ldmx4(al[i], AlS + off);
            }
            #pragma unroll
            for (int jp = 0; jp < 2; jp++) {
                uint32_t off = SW128((uint32_t)((nbase + jp*16 + ((bg >> 1) << 3) + brow_in) * 128
                                                + ks*32 + ((bg & 1) << 4)));
                uint32_t r[4];
                ldmx4(r, BhS + off);
                bh[jp*2][0] = r[0]; bh[jp*2][1] = r[1];
                bh[jp*2+1][0] = r[2]; bh[jp*2+1][1] = r[3];
                ldmx4(r, BlS + off);
                bl[jp*2][0] = r[0]; bl[jp*2][1] = r[1];
                bl[jp*2+1][0] = r[2]; bl[jp*2+1][1] = r[3];
            }
            #pragma unroll
            for (int i = 0; i < 4; i++)
                #pragma unroll
                for (int j = 0; j < 4; j++) {
                    mma16816(acc[i][j], ah[i], bh[j]);
                    mma16816(acc[i][j], ah[i], bl[j]);
                    mma16816(acc[i][j], al[i], bh[j]);
                }
        }
        if (kc < 7) {
            STS_A(buf ^ 1);
            CP_WAIT0();
        }
        __syncthreads();
        buf ^= 1;
    }

    // ---- epilogue: assemble groups of 4 consecutive cols via lane-pair shfl ----
    bool evenlane = (lane & 1) == 0;
    #pragma unroll
    for (int i = 0; i < 4; i++) {
        int row_local = mbase + i*16 + (lane >> 2) + ((lane & 1) ? 8 : 0);
        int token = m0 + row_local;
        float R00=0,R01=0,R02=0,R10=0,R11=0,R12=0,R20=0,R21=0,R22=0,T0=0,T1=0,T2=0;
        int which = 0, h = 0, b = 0, n = 0;
        if (mode == 0) {
            const float* R = rot + (size_t)token * 9;
            const float* T = tr + (size_t)token * 3;
            R00=R[0];R01=R[1];R02=R[2];R10=R[3];R11=R[4];R12=R[5];R20=R[6];R21=R[7];R22=R[8];
            T0=T[0];T1=T[1];T2=T[2];
            which = n0 >> 9;
            b = token >> 10; n = token & (NN - 1);
        }
        #pragma unroll
        for (int j = 0; j < 4; j++) {
            float x0 = __shfl_xor_sync(0xffffffffu, acc[i][j][0], 1);
            float x1 = __shfl_xor_sync(0xffffffffu, acc[i][j][1], 1);
            float x2 = __shfl_xor_sync(0xffffffffu, acc[i][j][2], 1);
            float x3 = __shfl_xor_sync(0xffffffffu, acc[i][j][3], 1);
            float v0, v1, v2, v3;
            if (evenlane) { v0 = acc[i][j][0]; v1 = acc[i][j][1]; v2 = x0; v3 = x1; }
            else          { v0 = x2; v1 = x3; v2 = acc[i][j][2]; v3 = acc[i][j][3]; }
            int cg = nbase + j*8 + ((lane >> 1) & 1) * 4;   // local col group base
            int cgl = n0 + cg;
            v0 += bias[cgl+0]; v1 += bias[cgl+1]; v2 += bias[cgl+2]; v3 += bias[cgl+3];
            if (mode == 0) {
                int hh2 = (cgl & 511) >> 6;
                int d = cgl & 63;
                float y0 = R00*v0 + R01*v1 + R02*v2;
                float y1 = R10*v0 + R11*v1 + R12*v2;
                float y2 = R20*v0 + R21*v1 + R22*v2;
                float y3;
                if (which == 0) {
                    y3 = v3 - (T0*y0 + T1*y1 + T2*y2);
                } else {
                    y0 += T0 * v3; y1 += T1 * v3; y2 += T2 * v3;
                    y3 = v3;
                }
                float* dstbuf = (which == 0) ? g_q : (which == 1 ? g_k : g_v);
                size_t o = ((size_t)(b * HH + hh2) * NN + n) * DH + d;
                float4 ov; ov.x=y0; ov.y=y1; ov.z=y2; ov.w=y3;
                *(float4*)(dstbuf + o) = ov;
            } else {
                float4 ov; ov.x=v0; ov.y=v1; ov.z=v2; ov.w=v3;
                *(float4*)(outp + (size_t)token * 512 + cgl) = ov;
            }
        }
    }
    #undef LOAD_A_REGS
    #undef STS_A
    #undef LOAD_B_ASYNC
}

// ===================== SIMT flash attention (unchanged) =====================
#define SQ 68
#define SKK 65
#define SV 68
#define SS 68

__global__ __launch_bounds__(256, 2) void attn_kernel(
    const float* __restrict__ rot, const float* __restrict__ tr)
{
    extern __shared__ float sm[];
    float* qs = sm;
    float* ks = qs + 128 * SQ;
    float* vs = ks + 64 * SKK;
    float* ss = vs + 64 * SV;
    float* alpha_sh = ss + 128 * SS;
    float* rinv_sh  = alpha_sh + 128;

    int t = threadIdx.x;
    int bh = blockIdx.y;
    int q0 = blockIdx.x << 7;
    const float* qptr  = g_q + ((size_t)bh * NN + q0) * DH;
    const float* kbase = g_k + (size_t)bh * NN * DH;
    const float* vbase = g_v + (size_t)bh * NN * DH;

    const float scale = 0.125f;
    for (int i = t; i < 2048; i += 256) {
        float4 v = *(const float4*)(qptr + (size_t)i * 4);
        int n = i >> 4, d0 = (i & 15) * 4;
        float4 o; o.x=v.x*scale; o.y=v.y*scale; o.z=v.z*scale; o.w=v.w*scale;
        *(float4*)&qs[n*SQ + d0] = o;
    }

    int qg = t >> 4, kg = t & 15;
    int qq = t >> 1, sub = t & 1;

    float acc[8][4] = {};
    float run_max = -1e30f, run_sum = 0.f;

    for (int kc = 0; kc < NN; kc += 64) {
        const float* kp = kbase + (size_t)kc * DH;
        const float* vp = vbase + (size_t)kc * DH;
        for (int i = t; i < 1024; i += 256) {
            float4 kv4 = *(const float4*)(kp + (size_t)i * 4);
            float4 vv4 = *(const float4*)(vp + (size_t)i * 4);
            int n = i >> 4, d0 = (i & 15) * 4;
            ks[n*SKK + d0+0]=kv4.x; ks[n*SKK + d0+1]=kv4.y;
            ks[n*SKK + d0+2]=kv4.z; ks[n*SKK + d0+3]=kv4.w;
            *(float4*)&vs[n*SV + d0] = vv4;
        }
        __syncthreads();

        float s[8][4] = {};
        #pragma unroll 8
        for (int dd = 0; dd < 64; dd++) {
            float qv[8], kv[4];
            #pragma unroll
            for (int i = 0; i < 8; i++) qv[i] = qs[(qg*8+i)*SQ + dd];
            #pragma unroll
            for (int j = 0; j < 4; j++) kv[j] = ks[(kg*4+j)*SKK + dd];
            #pragma unroll
            for (int i = 0; i < 8; i++)
                #pragma unroll
                for (int j = 0; j < 4; j++) s[i][j] += qv[i] * kv[j];
        }
        #pragma unroll
        for (int i = 0; i < 8; i++) {
            float4 o; o.x=s[i][0]; o.y=s[i][1]; o.z=s[i][2]; o.w=s[i][3];
            *(float4*)&ss[(qg*8+i)*SS + kg*4] = o;
        }
        __syncthreads();

        float* row = ss + qq*SS + sub*32;
        float mloc = -1e30f;
        #pragma unroll
        for (int i4 = 0; i4 < 8; i4++) {
            float4 v = *(const float4*)&row[i4*4];
            mloc = fmaxf(mloc, fmaxf(fmaxf(v.x, v.y), fmaxf(v.z, v.w)));
        }
        mloc = fmaxf(mloc, __shfl_xor_sync(0xffffffffu, mloc, 1));
        float nmax = fmaxf(run_max, mloc);
        float al = __expf(run_max - nmax);
        float psum = 0.f;
        #pragma unroll
        for (int i4 = 0; i4 < 8; i4++) {
            float4 v = *(const float4*)&row[i4*4];
            v.x = __expf(v.x - nmax); v.y = __expf(v.y - nmax);
            v.z = __expf(v.z - nmax); v.w = __expf(v.w - nmax);
            psum += v.x + v.y + v.z + v.w;
            *(float4*)&row[i4*4] = v;
        }
        psum += __shfl_xor_sync(0xffffffffu, psum, 1);
        run_sum = run_sum * al + psum;
        run_max = nmax;
        if (sub == 0) alpha_sh[qq] = al;
        __syncthreads();

        float alv[8];
        #pragma unroll
        for (int i = 0; i < 8; i++) alv[i] = alpha_sh[qg*8+i];
        #pragma unroll
        for (int i = 0; i < 8; i++)
            #pragma unroll
            for (int j = 0; j < 4; j++) acc[i][j] *= alv[i];
        #pragma unroll 4
        for (int k = 0; k < 64; k++) {
            float p[8];
            #pragma unroll
            for (int i = 0; i < 8; i++) p[i] = ss[(qg*8+i)*SS + k];
            float4 vv = *(const float4*)&vs[k*SV + kg*4];
            #pragma unroll
            for (int i = 0; i < 8; i++) {
                acc[i][0] += p[i] * vv.x;
                acc[i][1] += p[i] * vv.y;
                acc[i][2] += p[i] * vv.z;
                acc[i][3] += p[i] * vv.w;
            }
        }
        __syncthreads();
    }

    if (sub == 0) rinv_sh[qq] = 1.f / run_sum;
    __syncthreads();

    int b = bh >> 3, h = bh & 7;
    #pragma unroll
    for (int i = 0; i < 8; i++) {
        int nq = q0 + qg*8 + i;
        int token = b * NN + nq;
        float inv = rinv_sh[qg*8+i];
        float v0 = acc[i][0]*inv, v1 = acc[i][1]*inv;
        float v2 = acc[i][2]*inv, v3 = acc[i][3]*inv;
        const float* R = rot + (size_t)token * 9;
        const float* T = tr + (size_t)token * 3;
        float x0 = v0 - T[0]*v3, x1 = v1 - T[1]*v3, x2 = v2 - T[2]*v3;
        float y0 = R[0]*x0 + R[3]*x1 + R[6]*x2;
        float y1 = R[1]*x0 + R[4]*x1 + R[7]*x2;
        float y2 = R[2]*x0 + R[5]*x1 + R[8]*x2;
        float4 o; o.x=y0; o.y=y1; o.z=y2; o.w=v3;
        *(float4*)(g_att + (size_t)token * INNER + h * DH + kg * 4) = o;
    }
}

// ---------------------------------------------------------------------------
extern "C" void kernel_launch(void* const* d_in, const int* in_sizes, int n_in,
                              void* d_out, int out_size)
{
    const float* x     = (const float*)d_in[0];
    const float* rot   = (const float*)d_in[1];
    const float* tr    = (const float*)d_in[2];
    const float* w_qkv = (const float*)d_in[3];
    const float* b_qkv = (const float*)d_in[4];
    const float* w_out = (const float*)d_in[5];
    const float* b_out = (const float*)d_in[6];
    float* out = (float*)d_out;

    __nv_bfloat16 *wqT_h, *wqT_l, *woT_h, *woT_l;
    cudaGetSymbolAddress((void**)&wqT_h, g_wqkvT_h);
    cudaGetSymbolAddress((void**)&wqT_l, g_wqkvT_l);
    cudaGetSymbolAddress((void**)&woT_h, g_woutT_h);
    cudaGetSymbolAddress((void**)&woT_l, g_woutT_l);
    float* attp;
    cudaGetSymbolAddress((void**)&attp, g_att);

    // W transpose + bf16 split
    transpose_split_kernel<<<dim3(48, 16), dim3(32, 8)>>>(w_qkv, wqT_h, wqT_l, 512, 1536);
    transpose_split_kernel<<<dim3(16, 16), dim3(32, 8)>>>(w_out, woT_h, woT_l, 512, 512);

    // mma.sync GEMMs: 2 x 64KB double-buffered smem
    int mma_smem = 2 * 65536 + 128;
    cudaFuncSetAttribute(mma_gemm_kernel, cudaFuncAttributeMaxDynamicSharedMemorySize, mma_smem);

    // qkv: M=8192, Ntot=1536
    mma_gemm_kernel<<<dim3(12, 64), 256, mma_smem>>>(x, wqT_h, wqT_l, b_qkv, rot, tr, nullptr, 0);

    // attention (SIMT fp32)
    size_t shmem = (size_t)(128*SQ + 64*SKK + 64*SV + 128*SS + 256) * sizeof(float);
    cudaFuncSetAttribute(attn_kernel, cudaFuncAttributeMaxDynamicSharedMemorySize, (int)shmem);
    attn_kernel<<<dim3(8, 64), 256, shmem>>>(rot, tr);

    // out projection: M=8192, Ntot=512
    mma_gemm_kernel<<<dim3(4, 64), 256, mma_smem>>>(attp, woT_h, woT_l, b_out, nullptr, nullptr, out, 1);
}

// round 5
// speedup vs baseline: 3.2669x; 1.9510x over previous
#include <cuda_runtime.h>
#include <cuda_bf16.h>
#include <cstdint>
#include <math.h>

#define BB 8
#define NN 1024
#define DIMM 512
#define HH 8
#define DH 64
#define NTOK (BB*NN)          // 8192
#define INNER (HH*DH)         // 512

// Scratch (allocation-free rule: __device__ globals)
__device__ float g_att[(size_t)NTOK*INNER];
__device__ __nv_bfloat16 g_wqkvT_h[3*INNER*DIMM];
__device__ __nv_bfloat16 g_wqkvT_l[3*INNER*DIMM];
__device__ __nv_bfloat16 g_woutT_h[DIMM*INNER];
__device__ __nv_bfloat16 g_woutT_l[DIMM*INNER];
// pre-split bf16 q/k/v, head-major [bh][n][64]; q pre-scaled by DH^-0.5
__device__ __nv_bfloat16 g_qh[BB*HH*NN*DH];
__device__ __nv_bfloat16 g_ql[BB*HH*NN*DH];
__device__ __nv_bfloat16 g_kh[BB*HH*NN*DH];
__device__ __nv_bfloat16 g_kl[BB*HH*NN*DH];
__device__ __nv_bfloat16 g_vh[BB*HH*NN*DH];
__device__ __nv_bfloat16 g_vl[BB*HH*NN*DH];

// ===================== helpers =====================
__device__ __forceinline__ uint32_t smem_to_u32(const void* p) {
    uint32_t a;
    asm("{ .reg .u64 t; cvta.to.shared.u64 t, %1; cvt.u32.u64 %0, t; }"
        : "=r"(a) : "l"(p));
    return a;
}
#define SW128(o) ((o) ^ (((o) >> 3) & 0x70))

__device__ __forceinline__ void ldmx4(uint32_t* r, uint32_t a) {
    asm volatile("ldmatrix.sync.aligned.m8n8.x4.shared.b16 {%0,%1,%2,%3}, [%4];"
        : "=r"(r[0]), "=r"(r[1]), "=r"(r[2]), "=r"(r[3]) : "r"(a));
}
__device__ __forceinline__ void ldmx4t(uint32_t* r, uint32_t a) {
    asm volatile("ldmatrix.sync.aligned.m8n8.x4.trans.shared.b16 {%0,%1,%2,%3}, [%4];"
        : "=r"(r[0]), "=r"(r[1]), "=r"(r[2]), "=r"(r[3]) : "r"(a));
}
__device__ __forceinline__ void mma16816(float* d, const uint32_t* a, const uint32_t* b) {
    asm volatile("mma.sync.aligned.m16n8k16.row.col.f32.bf16.bf16.f32 "
        "{%0,%1,%2,%3}, {%4,%5,%6,%7}, {%8,%9}, {%0,%1,%2,%3};"
        : "+f"(d[0]), "+f"(d[1]), "+f"(d[2]), "+f"(d[3])
        : "r"(a[0]), "r"(a[1]), "r"(a[2]), "r"(a[3]), "r"(b[0]), "r"(b[1]));
}
__device__ __forceinline__ void cp16(uint32_t dst, const void* src) {
    asm volatile("cp.async.cg.shared.global [%0], [%1], 16;" :: "r"(dst), "l"(src));
}
#define CP_COMMIT() asm volatile("cp.async.commit_group;" ::: "memory")
#define CP_WAIT(n)  asm volatile("cp.async.wait_group %0;" :: "n"(n) : "memory")

__device__ __forceinline__ uint32_t pack_bf16(float lo, float hi) {
    uint32_t r;
    asm("cvt.rn.bf16x2.f32 %0, %1, %2;" : "=r"(r) : "f"(hi), "f"(lo));
    return r;
}

// ===================== transpose + bf16-split of W =====================
__global__ void transpose_split_kernel(const float* __restrict__ src,
                                       __nv_bfloat16* __restrict__ dh,
                                       __nv_bfloat16* __restrict__ dl,
                                       int K, int N)
{
    __shared__ float ts[32][33];
    int n0 = blockIdx.x << 5, k0 = blockIdx.y << 5;
    int tx = threadIdx.x, ty = threadIdx.y;
    #pragma unroll
    for (int i = 0; i < 32; i += 8)
        ts[ty + i][tx] = src[(size_t)(k0 + ty + i) * N + n0 + tx];
    __syncthreads();
    #pragma unroll
    for (int i = 0; i < 32; i += 8) {
        float v = ts[tx][ty + i];
        __nv_bfloat16 h = __float2bfloat16(v);
        float lo = v - __bfloat162float(h);
        size_t o = (size_t)(n0 + ty + i) * K + k0 + tx;
        dh[o] = h;
        dl[o] = __float2bfloat16(lo);
    }
}

// ===================== mma.sync bf16-split GEMM =====================
// mode 0: qkv (pose epilogue -> split bf16 q/k/v bufs), mode 1: out proj
__global__ __launch_bounds__(256, 1) void mma_gemm_kernel(
    const float* __restrict__ A,
    const __nv_bfloat16* __restrict__ Bh,
    const __nv_bfloat16* __restrict__ Bl,
    const float* __restrict__ bias,
    const float* __restrict__ rot, const float* __restrict__ tr,
    float* __restrict__ outp, int mode)
{
    extern __shared__ char smem[];
    uint32_t base = (smem_to_u32(smem) + 127) & ~127u;
    int t = threadIdx.x, lane = t & 31, w = t >> 5;
    int m0 = blockIdx.y << 7, n0 = blockIdx.x << 7;
    int mbase = (w >> 2) * 64, nbase = (w & 3) * 32;

    int rowc[4], k8c[4]; uint32_t swc[4];
    #pragma unroll
    for (int c = 0; c < 4; c++) {
        int ci = t + c * 256;
        rowc[c] = ci >> 3; k8c[c] = ci & 7;
        swc[c] = SW128((uint32_t)(rowc[c] * 128 + k8c[c] * 16));
    }

    float acc[4][4][4] = {};
    uint32_t pah[4][4], pal[4][4];

    #define LOAD_A_REGS(kc) do { \
        _Pragma("unroll") \
        for (int c = 0; c < 4; c++) { \
            const float* ap = A + (size_t)(m0 + rowc[c]) * 512 + (kc) * 64 + k8c[c] * 8; \
            float4 f0 = *(const float4*)ap; \
            float4 f1 = *(const float4*)(ap + 4); \
            uint32_t h0 = pack_bf16(f0.x, f0.y), h1 = pack_bf16(f0.z, f0.w); \
            uint32_t h2 = pack_bf16(f1.x, f1.y), h3 = pack_bf16(f1.z, f1.w); \
            float r0 = f0.x - __uint_as_float(h0 << 16); \
            float r1 = f0.y - __uint_as_float(h0 & 0xFFFF0000u); \
            float r2 = f0.z - __uint_as_float(h1 << 16); \
            float r3 = f0.w - __uint_as_float(h1 & 0xFFFF0000u); \
            float r4 = f1.x - __uint_as_float(h2 << 16); \
            float r5 = f1.y - __uint_as_float(h2 & 0xFFFF0000u); \
            float r6 = f1.z - __uint_as_float(h3 << 16); \
            float r7 = f1.w - __uint_as_float(h3 & 0xFFFF0000u); \
            pah[c][0] = h0; pah[c][1] = h1; pah[c][2] = h2; pah[c][3] = h3; \
            pal[c][0] = pack_bf16(r0, r1); pal[c][1] = pack_bf16(r2, r3); \
            pal[c][2] = pack_bf16(r4, r5); pal[c][3] = pack_bf16(r6, r7); \
        } \
    } while (0)

    #define STS_A(bb) do { \
        uint32_t bA = base + (bb) * 65536; \
        _Pragma("unroll") \
        for (int c = 0; c < 4; c++) { \
            uint4 hv = make_uint4(pah[c][0], pah[c][1], pah[c][2], pah[c][3]); \
            uint4 lv = make_uint4(pal[c][0], pal[c][1], pal[c][2], pal[c][3]); \
            *(uint4*)(smem + (bA + swc[c] - smem_to_u32(smem)))           = hv; \
            *(uint4*)(smem + (bA + 16384 + swc[c] - smem_to_u32(smem)))   = lv; \
        } \
    } while (0)

    #define LOAD_B_ASYNC(kc, bb) do { \
        uint32_t bB = base + (bb) * 65536 + 32768; \
        _Pragma("unroll") \
        for (int c = 0; c < 4; c++) { \
            const __nv_bfloat16* gh = Bh + (size_t)(n0 + rowc[c]) * 512 + (kc) * 64 + k8c[c] * 8; \
            const __nv_bfloat16* gl = Bl + (size_t)(n0 + rowc[c]) * 512 + (kc) * 64 + k8c[c] * 8; \
            cp16(bB + swc[c], gh); \
            cp16(bB + 16384 + swc[c], gl); \
        } \
        CP_COMMIT(); \
    } while (0)

    int arow = lane & 15;
    int acolb = (lane >> 4) * 16;
    int bg = lane >> 3;
    int brow_in = lane & 7;

    LOAD_B_ASYNC(0, 0);
    LOAD_A_REGS(0);
    STS_A(0);
    CP_WAIT(0);
    __syncthreads();

    int buf = 0;
    for (int kc = 0; kc < 8; kc++) {
        if (kc < 7) {
            LOAD_B_ASYNC(kc + 1, buf ^ 1);
            LOAD_A_REGS(kc + 1);
        }
        uint32_t AhS = base + buf * 65536;
        uint32_t AlS = AhS + 16384;
        uint32_t BhS = AhS + 32768;
        uint32_t BlS = AhS + 49152;
        #pragma unroll
        for (int ks = 0; ks < 4; ks++) {
            uint32_t ah[4][4], al[4][4], bhf[4][2], blf[4][2];
            #pragma unroll
            for (int i = 0; i < 4; i++) {
                uint32_t off = SW128((uint32_t)((mbase + i*16 + arow) * 128 + ks*32 + acolb));
                ldmx4(ah[i], AhS + off);
                ldmx4(al[i], AlS + off);
            }
            #pragma unroll
            for (int jp = 0; jp < 2; jp++) {
                uint32_t off = SW128((uint32_t)((nbase + jp*16 + ((bg >> 1) << 3) + brow_in) * 128
                                                + ks*32 + ((bg & 1) << 4)));
                uint32_t r[4];
                ldmx4(r, BhS + off);
                bhf[jp*2][0] = r[0]; bhf[jp*2][1] = r[1];
                bhf[jp*2+1][0] = r[2]; bhf[jp*2+1][1] = r[3];
                ldmx4(r, BlS + off);
                blf[jp*2][0] = r[0]; blf[jp*2][1] = r[1];
                blf[jp*2+1][0] = r[2]; blf[jp*2+1][1] = r[3];
            }
            #pragma unroll
            for (int i = 0; i < 4; i++)
                #pragma unroll
                for (int j = 0; j < 4; j++) {
                    mma16816(acc[i][j], ah[i], bhf[j]);
                    mma16816(acc[i][j], ah[i], blf[j]);
                    mma16816(acc[i][j], al[i], bhf[j]);
                }
        }
        if (kc < 7) {
            STS_A(buf ^ 1);
            CP_WAIT(0);
        }
        __syncthreads();
        buf ^= 1;
    }

    bool evenlane = (lane & 1) == 0;
    #pragma unroll
    for (int i = 0; i < 4; i++) {
        int row_local = mbase + i*16 + (lane >> 2) + ((lane & 1) ? 8 : 0);
        int token = m0 + row_local;
        float R00=0,R01=0,R02=0,R10=0,R11=0,R12=0,R20=0,R21=0,R22=0,T0=0,T1=0,T2=0;
        int which = 0, b = 0, n = 0;
        if (mode == 0) {
            const float* R = rot + (size_t)token * 9;
            const float* T = tr + (size_t)token * 3;
            R00=R[0];R01=R[1];R02=R[2];R10=R[3];R11=R[4];R12=R[5];R20=R[6];R21=R[7];R22=R[8];
            T0=T[0];T1=T[1];T2=T[2];
            which = n0 >> 9;
            b = token >> 10; n = token & (NN - 1);
        }
        #pragma unroll
        for (int j = 0; j < 4; j++) {
            float x0 = __shfl_xor_sync(0xffffffffu, acc[i][j][0], 1);
            float x1 = __shfl_xor_sync(0xffffffffu, acc[i][j][1], 1);
            float x2 = __shfl_xor_sync(0xffffffffu, acc[i][j][2], 1);
            float x3 = __shfl_xor_sync(0xffffffffu, acc[i][j][3], 1);
            float v0, v1, v2, v3;
            if (evenlane) { v0 = acc[i][j][0]; v1 = acc[i][j][1]; v2 = x0; v3 = x1; }
            else          { v0 = x2; v1 = x3; v2 = acc[i][j][2]; v3 = acc[i][j][3]; }
            int cg = nbase + j*8 + ((lane >> 1) & 1) * 4;
            int cgl = n0 + cg;
            v0 += bias[cgl+0]; v1 += bias[cgl+1]; v2 += bias[cgl+2]; v3 += bias[cgl+3];
            if (mode == 0) {
                int hh2 = (cgl & 511) >> 6;
                int d = cgl & 63;
                float y0 = R00*v0 + R01*v1 + R02*v2;
                float y1 = R10*v0 + R11*v1 + R12*v2;
                float y2 = R20*v0 + R21*v1 + R22*v2;
                float y3;
                if (which == 0) {
                    y3 = v3 - (T0*y0 + T1*y1 + T2*y2);
                    y0 *= 0.125f; y1 *= 0.125f; y2 *= 0.125f; y3 *= 0.125f;
                } else {
                    y0 += T0 * v3; y1 += T1 * v3; y2 += T2 * v3;
                    y3 = v3;
                }
                __nv_bfloat16* bufh = (which == 0) ? g_qh : (which == 1 ? g_kh : g_vh);
                __nv_bfloat16* bufl = (which == 0) ? g_ql : (which == 1 ? g_kl : g_vl);
                size_t o = ((size_t)(b * HH + hh2) * NN + n) * DH + d;
                uint32_t h01 = pack_bf16(y0, y1), h23 = pack_bf16(y2, y3);
                float l0 = y0 - __uint_as_float(h01 << 16);
                float l1 = y1 - __uint_as_float(h01 & 0xFFFF0000u);
                float l2 = y2 - __uint_as_float(h23 << 16);
                float l3 = y3 - __uint_as_float(h23 & 0xFFFF0000u);
                uint2 hv; hv.x = h01; hv.y = h23;
                uint2 lv; lv.x = pack_bf16(l0, l1); lv.y = pack_bf16(l2, l3);
                *(uint2*)(bufh + o) = hv;
                *(uint2*)(bufl + o) = lv;
            } else {
                float4 ov; ov.x=v0; ov.y=v1; ov.z=v2; ov.w=v3;
                *(float4*)(outp + (size_t)token * 512 + cgl) = ov;
            }
        }
    }
    #undef LOAD_A_REGS
    #undef STS_A
    #undef LOAD_B_ASYNC
}

// ===================== mma.sync flash attention =====================
// 128 queries/CTA, 8 warps x 16 queries, key chunks of 128, double-buffered.
// smem: buf{0,1}: KH 16K | KL 16K | VH 16K | VL 16K ; Q stage: QH 16K | QL 16K
#define ABUF 65536
#define AKH 0
#define AKL 16384
#define AVH 32768
#define AVL 49152
#define AQH 131072
#define AQL 147456

__global__ __launch_bounds__(256, 1) void attn_kernel(
    const float* __restrict__ rot, const float* __restrict__ tr)
{
    extern __shared__ char smem[];
    uint32_t base = (smem_to_u32(smem) + 127) & ~127u;
    int t = threadIdx.x, lane = t & 31, w = t >> 5;
    int bh = blockIdx.y;
    int q0 = blockIdx.x << 7;
    int wm = w << 4;   // warp's query base within tile

    // loader indexing (4 x 16B chunks per thread per 16KB tile)
    int rowc[4], k8c[4]; uint32_t swc[4];
    #pragma unroll
    for (int c = 0; c < 4; c++) {
        int ci = t + c * 256;
        rowc[c] = ci >> 3; k8c[c] = ci & 7;
        swc[c] = SW128((uint32_t)(rowc[c] * 128 + k8c[c] * 16));
    }
    const size_t bhbase = (size_t)bh * NN * DH;

    #define LOAD_KV(cc, bb) do { \
        uint32_t bp = base + (bb) * ABUF; \
        _Pragma("unroll") \
        for (int c = 0; c < 4; c++) { \
            size_t go = bhbase + ((size_t)((cc) * 128 + rowc[c])) * 64 + k8c[c] * 8; \
            cp16(bp + AKH + swc[c], g_kh + go); \
            cp16(bp + AKL + swc[c], g_kl + go); \
            cp16(bp + AVH + swc[c], g_vh + go); \
            cp16(bp + AVL + swc[c], g_vl + go); \
        } \
        CP_COMMIT(); \
    } while (0)

    // stage Q (hi/lo) + first KV chunk
    {
        #pragma unroll
        for (int c = 0; c < 4; c++) {
            size_t go = bhbase + ((size_t)(q0 + rowc[c])) * 64 + k8c[c] * 8;
            cp16(base + AQH + swc[c], g_qh + go);
            cp16(base + AQL + swc[c], g_ql + go);
        }
        CP_COMMIT();
    }
    LOAD_KV(0, 0);
    CP_WAIT(1);           // Q stage done
    __syncthreads();

    // Q fragments, register-resident for all chunks
    uint32_t qfh[4][4], qfl[4][4];
    #pragma unroll
    for (int ks = 0; ks < 4; ks++) {
        uint32_t off = SW128((uint32_t)((wm + (lane & 15)) * 128 + ks * 32 + (lane >> 4) * 16));
        ldmx4(qfh[ks], base + AQH + off);
        ldmx4(qfl[ks], base + AQL + off);
    }

    int bg = lane >> 3, brow_in = lane & 7;

    float acc[8][4] = {};
    float m1 = -1e30f, m2 = -1e30f, l1 = 0.f, l2 = 0.f;

    int buf = 0;
    for (int kc = 0; kc < 8; kc++) {
        if (kc < 7) LOAD_KV(kc + 1, buf ^ 1);
        CP_WAIT(1);
        if (kc == 7) CP_WAIT(0);
        __syncthreads();
        uint32_t KHs = base + buf * ABUF + AKH;
        uint32_t KLs = base + buf * ABUF + AKL;
        uint32_t VHs = base + buf * ABUF + AVH;
        uint32_t VLs = base + buf * ABUF + AVL;

        // ---- scores: 16 rows x 128 keys ----
        float s[16][4] = {};
        #pragma unroll
        for (int ks = 0; ks < 4; ks++) {
            #pragma unroll
            for (int jp = 0; jp < 8; jp++) {
                uint32_t off = SW128((uint32_t)((jp*16 + ((bg >> 1) << 3) + brow_in) * 128
                                                + ks*32 + ((bg & 1) << 4)));
                uint32_t rh[4], rl[4];
                ldmx4(rh, KHs + off);
                ldmx4(rl, KLs + off);
                uint32_t bh0[2] = {rh[0], rh[1]}, bh1[2] = {rh[2], rh[3]};
                uint32_t bl0[2] = {rl[0], rl[1]}, bl1[2] = {rl[2], rl[3]};
                mma16816(s[2*jp],   qfh[ks], bh0);
                mma16816(s[2*jp],   qfh[ks], bl0);
                mma16816(s[2*jp],   qfl[ks], bh0);
                mma16816(s[2*jp+1], qfh[ks], bh1);
                mma16816(s[2*jp+1], qfh[ks], bl1);
                mma16816(s[2*jp+1], qfl[ks], bh1);
            }
        }

        // ---- online softmax (rows r1=lane>>2, r2=r1+8) ----
        float mloc1 = -1e30f, mloc2 = -1e30f;
        #pragma unroll
        for (int nt = 0; nt < 16; nt++) {
            mloc1 = fmaxf(mloc1, fmaxf(s[nt][0], s[nt][1]));
            mloc2 = fmaxf(mloc2, fmaxf(s[nt][2], s[nt][3]));
        }
        mloc1 = fmaxf(mloc1, __shfl_xor_sync(0xffffffffu, mloc1, 1));
        mloc1 = fmaxf(mloc1, __shfl_xor_sync(0xffffffffu, mloc1, 2));
        mloc2 = fmaxf(mloc2, __shfl_xor_sync(0xffffffffu, mloc2, 1));
        mloc2 = fmaxf(mloc2, __shfl_xor_sync(0xffffffffu, mloc2, 2));
        float m1n = fmaxf(m1, mloc1), m2n = fmaxf(m2, mloc2);
        float a1 = __expf(m1 - m1n), a2 = __expf(m2 - m2n);
        m1 = m1n; m2 = m2n;

        uint32_t ph[8][4], pl[8][4];
        float ps1 = 0.f, ps2 = 0.f;
        #pragma unroll
        for (int kx = 0; kx < 8; kx++) {
            float p00 = __expf(s[2*kx][0]   - m1n);
            float p01 = __expf(s[2*kx][1]   - m1n);
            float p02 = __expf(s[2*kx][2]   - m2n);
            float p03 = __expf(s[2*kx][3]   - m2n);
            float p10 = __expf(s[2*kx+1][0] - m1n);
            float p11 = __expf(s[2*kx+1][1] - m1n);
            float p12 = __expf(s[2*kx+1][2] - m2n);
            float p13 = __expf(s[2*kx+1][3] - m2n);
            ps1 += p00 + p01 + p10 + p11;
            ps2 += p02 + p03 + p12 + p13;
            uint32_t h;
            h = pack_bf16(p00, p01); ph[kx][0] = h;
            pl[kx][0] = pack_bf16(p00 - __uint_as_float(h << 16),
                                  p01 - __uint_as_float(h & 0xFFFF0000u));
            h = pack_bf16(p02, p03); ph[kx][1] = h;
            pl[kx][1] = pack_bf16(p02 - __uint_as_float(h << 16),
                                  p03 - __uint_as_float(h & 0xFFFF0000u));
            h = pack_bf16(p10, p11); ph[kx][2] = h;
            pl[kx][2] = pack_bf16(p10 - __uint_as_float(h << 16),
                                  p11 - __uint_as_float(h & 0xFFFF0000u));
            h = pack_bf16(p12, p13); ph[kx][3] = h;
            pl[kx][3] = pack_bf16(p12 - __uint_as_float(h << 16),
                                  p13 - __uint_as_float(h & 0xFFFF0000u));
        }
        ps1 += __shfl_xor_sync(0xffffffffu, ps1, 1);
        ps1 += __shfl_xor_sync(0xffffffffu, ps1, 2);
        ps2 += __shfl_xor_sync(0xffffffffu, ps2, 1);
        ps2 += __shfl_xor_sync(0xffffffffu, ps2, 2);
        l1 = l1 * a1 + ps1;
        l2 = l2 * a2 + ps2;

        #pragma unroll
        for (int nt = 0; nt < 8; nt++) {
            acc[nt][0] *= a1; acc[nt][1] *= a1;
            acc[nt][2] *= a2; acc[nt][3] *= a2;
        }

        // ---- PV: P(16x128) @ V(128x64) ----
        #pragma unroll
        for (int kx = 0; kx < 8; kx++) {
            #pragma unroll
            for (int np = 0; np < 4; np++) {
                uint32_t off = SW128((uint32_t)((kx*16 + (lane & 15)) * 128
                                                + np*32 + (lane >> 4) * 16));
                uint32_t rh[4], rl[4];
                ldmx4t(rh, VHs + off);
                ldmx4t(rl, VLs + off);
                uint32_t vh0[2] = {rh[0], rh[1]}, vh1[2] = {rh[2], rh[3]};
                uint32_t vl0[2] = {rl[0], rl[1]}, vl1[2] = {rl[2], rl[3]};
                mma16816(acc[2*np],   ph[kx], vh0);
                mma16816(acc[2*np],   ph[kx], vl0);
                mma16816(acc[2*np],   pl[kx], vh0);
                mma16816(acc[2*np+1], ph[kx], vh1);
                mma16816(acc[2*np+1], ph[kx], vl1);
                mma16816(acc[2*np+1], pl[kx], vh1);
            }
        }
        __syncthreads();
        buf ^= 1;
    }

    // ---- epilogue: normalize + inverse pose + relayout ----
    float inv1 = 1.f / l1, inv2 = 1.f / l2;
    bool odd = lane & 1;
    float inv = odd ? inv2 : inv1;
    int r = (lane >> 2) + (odd ? 8 : 0);
    int nq = q0 + wm + r;
    int b = bh >> 3, h = bh & 7;
    int token = b * NN + nq;
    const float* R = rot + (size_t)token * 9;
    const float* T = tr + (size_t)token * 3;
    float R00=R[0],R01=R[1],R02=R[2],R10=R[3],R11=R[4],R12=R[5],R20=R[6],R21=R[7],R22=R[8];
    float T0=T[0],T1=T[1],T2=T[2];
    int grp = (lane >> 1) & 1;
    #pragma unroll
    for (int nt = 0; nt < 8; nt++) {
        float o0 = acc[nt][0], o1 = acc[nt][1], o2 = acc[nt][2], o3 = acc[nt][3];
        float x0 = __shfl_xor_sync(0xffffffffu, o0, 1);
        float x1 = __shfl_xor_sync(0xffffffffu, o1, 1);
        float x2 = __shfl_xor_sync(0xffffffffu, o2, 1);
        float x3 = __shfl_xor_sync(0xffffffffu, o3, 1);
        float v0, v1, v2, v3;
        if (!odd) { v0 = o0; v1 = o1; v2 = x0; v3 = x1; }   // row r1, dh pair + partner's
        else      { v0 = x2; v1 = x3; v2 = o2; v3 = o3; }   // row r2
        v0 *= inv; v1 *= inv; v2 *= inv; v3 *= inv;
        // inverse pose: y = R^T (v_{0:3} - T*v3); y3 = v3
        float u0 = v0 - T0*v3, u1 = v1 - T1*v3, u2 = v2 - T2*v3;
        float y0 = R00*u0 + R10*u1 + R20*u2;
        float y1 = R01*u0 + R11*u1 + R21*u2;
        float y2 = R02*u0 + R12*u1 + R22*u2;
        float4 ov; ov.x=y0; ov.y=y1; ov.z=y2; ov.w=v3;
        *(float4*)(g_att + (size_t)token * INNER + h * DH + nt * 8 + grp * 4) = ov;
    }
    #undef LOAD_KV
}

// ---------------------------------------------------------------------------
extern "C" void kernel_launch(void* const* d_in, const int* in_sizes, int n_in,
                              void* d_out, int out_size)
{
    const float* x     = (const float*)d_in[0];
    const float* rot   = (const float*)d_in[1];
    const float* tr    = (const float*)d_in[2];
    const float* w_qkv = (const float*)d_in[3];
    const float* b_qkv = (const float*)d_in[4];
    const float* w_out = (const float*)d_in[5];
    const float* b_out = (const float*)d_in[6];
    float* out = (float*)d_out;

    __nv_bfloat16 *wqT_h, *wqT_l, *woT_h, *woT_l;
    cudaGetSymbolAddress((void**)&wqT_h, g_wqkvT_h);
    cudaGetSymbolAddress((void**)&wqT_l, g_wqkvT_l);
    cudaGetSymbolAddress((void**)&woT_h, g_woutT_h);
    cudaGetSymbolAddress((void**)&woT_l, g_woutT_l);
    float* attp;
    cudaGetSymbolAddress((void**)&attp, g_att);

    transpose_split_kernel<<<dim3(48, 16), dim3(32, 8)>>>(w_qkv, wqT_h, wqT_l, 512, 1536);
    transpose_split_kernel<<<dim3(16, 16), dim3(32, 8)>>>(w_out, woT_h, woT_l, 512, 512);

    int mma_smem = 2 * 65536 + 128;
    cudaFuncSetAttribute(mma_gemm_kernel, cudaFuncAttributeMaxDynamicSharedMemorySize, mma_smem);

    // qkv: M=8192, Ntot=1536 -> split bf16 q/k/v
    mma_gemm_kernel<<<dim3(12, 64), 256, mma_smem>>>(x, wqT_h, wqT_l, b_qkv, rot, tr, nullptr, 0);

    // attention (mma.sync bf16-split flash)
    int attn_smem = 2 * ABUF + 32768 + 128;   // 160KB + pad
    cudaFuncSetAttribute(attn_kernel, cudaFuncAttributeMaxDynamicSharedMemorySize, attn_smem);
    attn_kernel<<<dim3(8, 64), 256, attn_smem>>>(rot, tr);

    // out projection: M=8192, Ntot=512
    mma_gemm_kernel<<<dim3(4, 64), 256, mma_smem>>>(attp, woT_h, woT_l, b_out, nullptr, nullptr, out, 1);
}

// round 6
// speedup vs baseline: 3.5188x; 1.0771x over previous
#include <cuda_runtime.h>
#include <cuda_bf16.h>
#include <cstdint>
#include <math.h>

#define BB 8
#define NN 1024
#define DIMM 512
#define HH 8
#define DH 64
#define NTOK (BB*NN)          // 8192
#define INNER (HH*DH)         // 512

// Scratch (allocation-free rule: __device__ globals)
__device__ __nv_bfloat16 g_xh[(size_t)NTOK*DIMM];
__device__ __nv_bfloat16 g_xl[(size_t)NTOK*DIMM];
__device__ __nv_bfloat16 g_atth[(size_t)NTOK*INNER];
__device__ __nv_bfloat16 g_attl[(size_t)NTOK*INNER];
__device__ __nv_bfloat16 g_wqkvT_h[3*INNER*DIMM];
__device__ __nv_bfloat16 g_wqkvT_l[3*INNER*DIMM];
__device__ __nv_bfloat16 g_woutT_h[DIMM*INNER];
__device__ __nv_bfloat16 g_woutT_l[DIMM*INNER];
// pre-split bf16 q/k/v, head-major [bh][n][64]; q pre-scaled by DH^-0.5 * log2(e)
__device__ __nv_bfloat16 g_qh[BB*HH*NN*DH];
__device__ __nv_bfloat16 g_ql[BB*HH*NN*DH];
__device__ __nv_bfloat16 g_kh[BB*HH*NN*DH];
__device__ __nv_bfloat16 g_kl[BB*HH*NN*DH];
__device__ __nv_bfloat16 g_vh[BB*HH*NN*DH];
__device__ __nv_bfloat16 g_vl[BB*HH*NN*DH];

// ===================== helpers =====================
__device__ __forceinline__ uint32_t smem_to_u32(const void* p) {
    uint32_t a;
    asm("{ .reg .u64 t; cvta.to.shared.u64 t, %1; cvt.u32.u64 %0, t; }"
        : "=r"(a) : "l"(p));
    return a;
}
#define SW128(o) ((o) ^ (((o) >> 3) & 0x70))

__device__ __forceinline__ void ldmx4(uint32_t* r, uint32_t a) {
    asm volatile("ldmatrix.sync.aligned.m8n8.x4.shared.b16 {%0,%1,%2,%3}, [%4];"
        : "=r"(r[0]), "=r"(r[1]), "=r"(r[2]), "=r"(r[3]) : "r"(a));
}
__device__ __forceinline__ void ldmx4t(uint32_t* r, uint32_t a) {
    asm volatile("ldmatrix.sync.aligned.m8n8.x4.trans.shared.b16 {%0,%1,%2,%3}, [%4];"
        : "=r"(r[0]), "=r"(r[1]), "=r"(r[2]), "=r"(r[3]) : "r"(a));
}
__device__ __forceinline__ void mma16816(float* d, const uint32_t* a, const uint32_t* b) {
    asm volatile("mma.sync.aligned.m16n8k16.row.col.f32.bf16.bf16.f32 "
        "{%0,%1,%2,%3}, {%4,%5,%6,%7}, {%8,%9}, {%0,%1,%2,%3};"
        : "+f"(d[0]), "+f"(d[1]), "+f"(d[2]), "+f"(d[3])
        : "r"(a[0]), "r"(a[1]), "r"(a[2]), "r"(a[3]), "r"(b[0]), "r"(b[1]));
}
__device__ __forceinline__ void cp16(uint32_t dst, const void* src) {
    asm volatile("cp.async.cg.shared.global [%0], [%1], 16;" :: "r"(dst), "l"(src));
}
#define CP_COMMIT() asm volatile("cp.async.commit_group;" ::: "memory")
#define CP_WAIT(n)  asm volatile("cp.async.wait_group %0;" :: "n"(n) : "memory")

__device__ __forceinline__ uint32_t pack_bf16(float lo, float hi) {
    uint32_t r;
    asm("cvt.rn.bf16x2.f32 %0, %1, %2;" : "=r"(r) : "f"(hi), "f"(lo));
    return r;
}
__device__ __forceinline__ float ex2f(float x) {
    float r; asm("ex2.approx.f32 %0, %1;" : "=f"(r) : "f"(x)); return r;
}

// ===================== elementwise fp32 -> split bf16 =====================
__global__ void split_kernel(const float* __restrict__ src,
                             __nv_bfloat16* __restrict__ dh,
                             __nv_bfloat16* __restrict__ dl)
{
    int i = blockIdx.x * 256 + threadIdx.x;
    float4 f = ((const float4*)src)[i];
    uint32_t h01 = pack_bf16(f.x, f.y), h23 = pack_bf16(f.z, f.w);
    float l0 = f.x - __uint_as_float(h01 << 16);
    float l1 = f.y - __uint_as_float(h01 & 0xFFFF0000u);
    float l2 = f.z - __uint_as_float(h23 << 16);
    float l3 = f.w - __uint_as_float(h23 & 0xFFFF0000u);
    uint2 hv; hv.x = h01; hv.y = h23;
    uint2 lv; lv.x = pack_bf16(l0, l1); lv.y = pack_bf16(l2, l3);
    ((uint2*)dh)[i] = hv;
    ((uint2*)dl)[i] = lv;
}

// ===================== transpose + bf16-split of W =====================
__global__ void transpose_split_kernel(const float* __restrict__ src,
                                       __nv_bfloat16* __restrict__ dh,
                                       __nv_bfloat16* __restrict__ dl,
                                       int K, int N)
{
    __shared__ float ts[32][33];
    int n0 = blockIdx.x << 5, k0 = blockIdx.y << 5;
    int tx = threadIdx.x, ty = threadIdx.y;
    #pragma unroll
    for (int i = 0; i < 32; i += 8)
        ts[ty + i][tx] = src[(size_t)(k0 + ty + i) * N + n0 + tx];
    __syncthreads();
    #pragma unroll
    for (int i = 0; i < 32; i += 8) {
        float v = ts[tx][ty + i];
        __nv_bfloat16 h = __float2bfloat16(v);
        float lo = v - __bfloat162float(h);
        size_t o = (size_t)(n0 + ty + i) * K + k0 + tx;
        dh[o] = h;
        dl[o] = __float2bfloat16(lo);
    }
}

// ===================== mma.sync bf16-split GEMM (pure cp.async) =====================
// C[M][Ntot] = A @ B^T, A/B both pre-split bf16 [rows][512].
// mode 0: qkv (pose epilogue -> split q/k/v), mode 1: out proj (bias -> outp)
__global__ __launch_bounds__(256, 1) void mma_gemm_kernel(
    const __nv_bfloat16* __restrict__ Ah,
    const __nv_bfloat16* __restrict__ Al,
    const __nv_bfloat16* __restrict__ Bh,
    const __nv_bfloat16* __restrict__ Bl,
    const float* __restrict__ bias,
    const float* __restrict__ rot, const float* __restrict__ tr,
    float* __restrict__ outp, int mode)
{
    extern __shared__ char smem[];
    uint32_t base = (smem_to_u32(smem) + 127) & ~127u;
    int t = threadIdx.x, lane = t & 31, w = t >> 5;
    int m0 = blockIdx.y << 7, n0 = blockIdx.x << 7;
    int mbase = (w >> 2) * 64, nbase = (w & 3) * 32;

    int rowc[4], k8c[4]; uint32_t swc[4];
    #pragma unroll
    for (int c = 0; c < 4; c++) {
        int ci = t + c * 256;
        rowc[c] = ci >> 3; k8c[c] = ci & 7;
        swc[c] = SW128((uint32_t)(rowc[c] * 128 + k8c[c] * 16));
    }

    float acc[4][4][4] = {};

    #define LOAD_ALL(kc, bb) do { \
        uint32_t bp = base + (bb) * 65536; \
        _Pragma("unroll") \
        for (int c = 0; c < 4; c++) { \
            size_t ga = (size_t)(m0 + rowc[c]) * 512 + (kc) * 64 + k8c[c] * 8; \
            size_t gb = (size_t)(n0 + rowc[c]) * 512 + (kc) * 64 + k8c[c] * 8; \
            cp16(bp +         swc[c], Ah + ga); \
            cp16(bp + 16384 + swc[c], Al + ga); \
            cp16(bp + 32768 + swc[c], Bh + gb); \
            cp16(bp + 49152 + swc[c], Bl + gb); \
        } \
        CP_COMMIT(); \
    } while (0)

    int arow = lane & 15;
    int acolb = (lane >> 4) * 16;
    int bg = lane >> 3;
    int brow_in = lane & 7;

    LOAD_ALL(0, 0);
    CP_WAIT(0);
    __syncthreads();

    int buf = 0;
    for (int kc = 0; kc < 8; kc++) {
        if (kc < 7) LOAD_ALL(kc + 1, buf ^ 1);
        uint32_t AhS = base + buf * 65536;
        uint32_t AlS = AhS + 16384;
        uint32_t BhS = AhS + 32768;
        uint32_t BlS = AhS + 49152;
        #pragma unroll
        for (int ks = 0; ks < 4; ks++) {
            uint32_t ah[4][4], al[4][4], bhf[4][2], blf[4][2];
            #pragma unroll
            for (int i = 0; i < 4; i++) {
                uint32_t off = SW128((uint32_t)((mbase + i*16 + arow) * 128 + ks*32 + acolb));
                ldmx4(ah[i], AhS + off);
                ldmx4(al[i], AlS + off);
            }
            #pragma unroll
            for (int jp = 0; jp < 2; jp++) {
                uint32_t off = SW128((uint32_t)((nbase + jp*16 + ((bg >> 1) << 3) + brow_in) * 128
                                                + ks*32 + ((bg & 1) << 4)));
                uint32_t r[4];
                ldmx4(r, BhS + off);
                bhf[jp*2][0] = r[0]; bhf[jp*2][1] = r[1];
                bhf[jp*2+1][0] = r[2]; bhf[jp*2+1][1] = r[3];
                ldmx4(r, BlS + off);
                blf[jp*2][0] = r[0]; blf[jp*2][1] = r[1];
                blf[jp*2+1][0] = r[2]; blf[jp*2+1][1] = r[3];
            }
            #pragma unroll
            for (int i = 0; i < 4; i++)
                #pragma unroll
                for (int j = 0; j < 4; j++) {
                    mma16816(acc[i][j], ah[i], bhf[j]);
                    mma16816(acc[i][j], ah[i], blf[j]);
                    mma16816(acc[i][j], al[i], bhf[j]);
                }
        }
        if (kc < 7) CP_WAIT(0);
        __syncthreads();
        buf ^= 1;
    }

    const float QSCALE = 0.125f * 1.44269504088896f;   // DH^-0.5 * log2(e)
    bool evenlane = (lane & 1) == 0;
    #pragma unroll
    for (int i = 0; i < 4; i++) {
        int row_local = mbase + i*16 + (lane >> 2) + ((lane & 1) ? 8 : 0);
        int token = m0 + row_local;
        float R00=0,R01=0,R02=0,R10=0,R11=0,R12=0,R20=0,R21=0,R22=0,T0=0,T1=0,T2=0;
        int which = 0, b = 0, n = 0;
        if (mode == 0) {
            const float* R = rot + (size_t)token * 9;
            const float* T = tr + (size_t)token * 3;
            R00=R[0];R01=R[1];R02=R[2];R10=R[3];R11=R[4];R12=R[5];R20=R[6];R21=R[7];R22=R[8];
            T0=T[0];T1=T[1];T2=T[2];
            which = n0 >> 9;
            b = token >> 10; n = token & (NN - 1);
        }
        #pragma unroll
        for (int j = 0; j < 4; j++) {
            float x0 = __shfl_xor_sync(0xffffffffu, acc[i][j][0], 1);
            float x1 = __shfl_xor_sync(0xffffffffu, acc[i][j][1], 1);
            float x2 = __shfl_xor_sync(0xffffffffu, acc[i][j][2], 1);
            float x3 = __shfl_xor_sync(0xffffffffu, acc[i][j][3], 1);
            float v0, v1, v2, v3;
            if (evenlane) { v0 = acc[i][j][0]; v1 = acc[i][j][1]; v2 = x0; v3 = x1; }
            else          { v0 = x2; v1 = x3; v2 = acc[i][j][2]; v3 = acc[i][j][3]; }
            int cg = nbase + j*8 + ((lane >> 1) & 1) * 4;
            int cgl = n0 + cg;
            v0 += bias[cgl+0]; v1 += bias[cgl+1]; v2 += bias[cgl+2]; v3 += bias[cgl+3];
            if (mode == 0) {
                int hh2 = (cgl & 511) >> 6;
                int d = cgl & 63;
                float y0 = R00*v0 + R01*v1 + R02*v2;
                float y1 = R10*v0 + R11*v1 + R12*v2;
                float y2 = R20*v0 + R21*v1 + R22*v2;
                float y3;
                if (which == 0) {
                    y3 = v3 - (T0*y0 + T1*y1 + T2*y2);
                    y0 *= QSCALE; y1 *= QSCALE; y2 *= QSCALE; y3 *= QSCALE;
                } else {
                    y0 += T0 * v3; y1 += T1 * v3; y2 += T2 * v3;
                    y3 = v3;
                }
                __nv_bfloat16* bufh = (which == 0) ? g_qh : (which == 1 ? g_kh : g_vh);
                __nv_bfloat16* bufl = (which == 0) ? g_ql : (which == 1 ? g_kl : g_vl);
                size_t o = ((size_t)(b * HH + hh2) * NN + n) * DH + d;
                uint32_t h01 = pack_bf16(y0, y1), h23 = pack_bf16(y2, y3);
                float l0 = y0 - __uint_as_float(h01 << 16);
                float l1 = y1 - __uint_as_float(h01 & 0xFFFF0000u);
                float l2 = y2 - __uint_as_float(h23 << 16);
                float l3 = y3 - __uint_as_float(h23 & 0xFFFF0000u);
                uint2 hv; hv.x = h01; hv.y = h23;
                uint2 lv; lv.x = pack_bf16(l0, l1); lv.y = pack_bf16(l2, l3);
                *(uint2*)(bufh + o) = hv;
                *(uint2*)(bufl + o) = lv;
            } else {
                float4 ov; ov.x=v0; ov.y=v1; ov.z=v2; ov.w=v3;
                *(float4*)(outp + (size_t)token * 512 + cgl) = ov;
            }
        }
    }
    #undef LOAD_ALL
}

// ===================== mma.sync flash attention =====================
#define ABUF 65536
#define AKH 0
#define AKL 16384
#define AVH 32768
#define AVL 49152
#define AQH 131072
#define AQL 147456

__global__ __launch_bounds__(256, 1) void attn_kernel(
    const float* __restrict__ rot, const float* __restrict__ tr)
{
    extern __shared__ char smem[];
    uint32_t base = (smem_to_u32(smem) + 127) & ~127u;
    int t = threadIdx.x, lane = t & 31, w = t >> 5;
    int bh = blockIdx.y;
    int q0 = blockIdx.x << 7;
    int wm = w << 4;

    int rowc[4], k8c[4]; uint32_t swc[4];
    #pragma unroll
    for (int c = 0; c < 4; c++) {
        int ci = t + c * 256;
        rowc[c] = ci >> 3; k8c[c] = ci & 7;
        swc[c] = SW128((uint32_t)(rowc[c] * 128 + k8c[c] * 16));
    }
    const size_t bhbase = (size_t)bh * NN * DH;

    #define LOAD_KV(cc, bb) do { \
        uint32_t bp = base + (bb) * ABUF; \
        _Pragma("unroll") \
        for (int c = 0; c < 4; c++) { \
            size_t go = bhbase + ((size_t)((cc) * 128 + rowc[c])) * 64 + k8c[c] * 8; \
            cp16(bp + AKH + swc[c], g_kh + go); \
            cp16(bp + AKL + swc[c], g_kl + go); \
            cp16(bp + AVH + swc[c], g_vh + go); \
            cp16(bp + AVL + swc[c], g_vl + go); \
        } \
        CP_COMMIT(); \
    } while (0)

    {
        #pragma unroll
        for (int c = 0; c < 4; c++) {
            size_t go = bhbase + ((size_t)(q0 + rowc[c])) * 64 + k8c[c] * 8;
            cp16(base + AQH + swc[c], g_qh + go);
            cp16(base + AQL + swc[c], g_ql + go);
        }
        CP_COMMIT();
    }
    LOAD_KV(0, 0);
    CP_WAIT(1);
    __syncthreads();

    uint32_t qfh[4][4], qfl[4][4];
    #pragma unroll
    for (int ks = 0; ks < 4; ks++) {
        uint32_t off = SW128((uint32_t)((wm + (lane & 15)) * 128 + ks * 32 + (lane >> 4) * 16));
        ldmx4(qfh[ks], base + AQH + off);
        ldmx4(qfl[ks], base + AQL + off);
    }

    int bg = lane >> 3, brow_in = lane & 7;

    float acc[8][4] = {};
    float m1 = -1e30f, m2 = -1e30f, l1 = 0.f, l2 = 0.f;

    int buf = 0;
    for (int kc = 0; kc < 8; kc++) {
        if (kc < 7) LOAD_KV(kc + 1, buf ^ 1);
        CP_WAIT(1);
        if (kc == 7) CP_WAIT(0);
        __syncthreads();
        uint32_t KHs = base + buf * ABUF + AKH;
        uint32_t KLs = base + buf * ABUF + AKL;
        uint32_t VHs = base + buf * ABUF + AVH;
        uint32_t VLs = base + buf * ABUF + AVL;

        // ---- scores (log2-domain): 16 rows x 128 keys ----
        float s[16][4] = {};
        #pragma unroll
        for (int ks = 0; ks < 4; ks++) {
            #pragma unroll
            for (int jp = 0; jp < 8; jp++) {
                uint32_t off = SW128((uint32_t)((jp*16 + ((bg >> 1) << 3) + brow_in) * 128
                                                + ks*32 + ((bg & 1) << 4)));
                uint32_t rh[4], rl[4];
                ldmx4(rh, KHs + off);
                ldmx4(rl, KLs + off);
                uint32_t bh0[2] = {rh[0], rh[1]}, bh1[2] = {rh[2], rh[3]};
                uint32_t bl0[2] = {rl[0], rl[1]}, bl1[2] = {rl[2], rl[3]};
                mma16816(s[2*jp],   qfh[ks], bh0);
                mma16816(s[2*jp],   qfh[ks], bl0);
                mma16816(s[2*jp],   qfl[ks], bh0);
                mma16816(s[2*jp+1], qfh[ks], bh1);
                mma16816(s[2*jp+1], qfh[ks], bl1);
                mma16816(s[2*jp+1], qfl[ks], bh1);
            }
        }

        // ---- max reduce ----
        float mloc1 = -1e30f, mloc2 = -1e30f;
        #pragma unroll
        for (int nt = 0; nt < 16; nt++) {
            mloc1 = fmaxf(mloc1, fmaxf(s[nt][0], s[nt][1]));
            mloc2 = fmaxf(mloc2, fmaxf(s[nt][2], s[nt][3]));
        }
        mloc1 = fmaxf(mloc1, __shfl_xor_sync(0xffffffffu, mloc1, 1));
        mloc1 = fmaxf(mloc1, __shfl_xor_sync(0xffffffffu, mloc1, 2));
        mloc2 = fmaxf(mloc2, __shfl_xor_sync(0xffffffffu, mloc2, 1));
        mloc2 = fmaxf(mloc2, __shfl_xor_sync(0xffffffffu, mloc2, 2));
        float m1n = fmaxf(m1, mloc1), m2n = fmaxf(m2, mloc2);
        float a1 = ex2f(m1 - m1n), a2 = ex2f(m2 - m2n);
        m1 = m1n; m2 = m2n;

        #pragma unroll
        for (int nt = 0; nt < 8; nt++) {
            acc[nt][0] *= a1; acc[nt][1] *= a1;
            acc[nt][2] *= a2; acc[nt][3] *= a2;
        }

        // ---- fused exp + pack + PV per 16-key slice ----
        float ps1 = 0.f, ps2 = 0.f;
        #pragma unroll
        for (int kx = 0; kx < 8; kx++) {
            float p00 = ex2f(s[2*kx][0]   - m1n);
            float p01 = ex2f(s[2*kx][1]   - m1n);
            float p02 = ex2f(s[2*kx][2]   - m2n);
            float p03 = ex2f(s[2*kx][3]   - m2n);
            float p10 = ex2f(s[2*kx+1][0] - m1n);
            float p11 = ex2f(s[2*kx+1][1] - m1n);
            float p12 = ex2f(s[2*kx+1][2] - m2n);
            float p13 = ex2f(s[2*kx+1][3] - m2n);
            ps1 += p00 + p01 + p10 + p11;
            ps2 += p02 + p03 + p12 + p13;
            uint32_t ph[4], pl[4], h;
            h = pack_bf16(p00, p01); ph[0] = h;
            pl[0] = pack_bf16(p00 - __uint_as_float(h << 16),
                              p01 - __uint_as_float(h & 0xFFFF0000u));
            h = pack_bf16(p02, p03); ph[1] = h;
            pl[1] = pack_bf16(p02 - __uint_as_float(h << 16),
                              p03 - __uint_as_float(h & 0xFFFF0000u));
            h = pack_bf16(p10, p11); ph[2] = h;
            pl[2] = pack_bf16(p10 - __uint_as_float(h << 16),
                              p11 - __uint_as_float(h & 0xFFFF0000u));
            h = pack_bf16(p12, p13); ph[3] = h;
            pl[3] = pack_bf16(p12 - __uint_as_float(h << 16),
                              p13 - __uint_as_float(h & 0xFFFF0000u));
            #pragma unroll
            for (int np = 0; np < 4; np++) {
                uint32_t off = SW128((uint32_t)((kx*16 + (lane & 15)) * 128
                                                + np*32 + (lane >> 4) * 16));
                uint32_t rh[4], rl[4];
                ldmx4t(rh, VHs + off);
                ldmx4t(rl, VLs + off);
                uint32_t vh0[2] = {rh[0], rh[1]}, vh1[2] = {rh[2], rh[3]};
                uint32_t vl0[2] = {rl[0], rl[1]}, vl1[2] = {rl[2], rl[3]};
                mma16816(acc[2*np],   ph, vh0);
                mma16816(acc[2*np],   ph, vl0);
                mma16816(acc[2*np],   pl, vh0);
                mma16816(acc[2*np+1], ph, vh1);
                mma16816(acc[2*np+1], ph, vl1);
                mma16816(acc[2*np+1], pl, vh1);
            }
        }
        ps1 += __shfl_xor_sync(0xffffffffu, ps1, 1);
        ps1 += __shfl_xor_sync(0xffffffffu, ps1, 2);
        ps2 += __shfl_xor_sync(0xffffffffu, ps2, 1);
        ps2 += __shfl_xor_sync(0xffffffffu, ps2, 2);
        l1 = l1 * a1 + ps1;
        l2 = l2 * a2 + ps2;

        __syncthreads();
        buf ^= 1;
    }

    // ---- epilogue: normalize + inverse pose + relayout -> split bf16 ----
    float inv1 = 1.f / l1, inv2 = 1.f / l2;
    bool odd = lane & 1;
    float inv = odd ? inv2 : inv1;
    int r = (lane >> 2) + (odd ? 8 : 0);
    int nq = q0 + wm + r;
    int b = bh >> 3, h = bh & 7;
    int token = b * NN + nq;
    const float* R = rot + (size_t)token * 9;
    const float* T = tr + (size_t)token * 3;
    float R00=R[0],R01=R[1],R02=R[2],R10=R[3],R11=R[4],R12=R[5],R20=R[6],R21=R[7],R22=R[8];
    float T0=T[0],T1=T[1],T2=T[2];
    int grp = (lane >> 1) & 1;
    #pragma unroll
    for (int nt = 0; nt < 8; nt++) {
        float o0 = acc[nt][0], o1 = acc[nt][1], o2 = acc[nt][2], o3 = acc[nt][3];
        float x0 = __shfl_xor_sync(0xffffffffu, o0, 1);
        float x1 = __shfl_xor_sync(0xffffffffu, o1, 1);
        float x2 = __shfl_xor_sync(0xffffffffu, o2, 1);
        float x3 = __shfl_xor_sync(0xffffffffu, o3, 1);
        float v0, v1, v2, v3;
        if (!odd) { v0 = o0; v1 = o1; v2 = x0; v3 = x1; }
        else      { v0 = x2; v1 = x3; v2 = o2; v3 = o3; }
        v0 *= inv; v1 *= inv; v2 *= inv; v3 *= inv;
        float u0 = v0 - T0*v3, u1 = v1 - T1*v3, u2 = v2 - T2*v3;
        float y0 = R00*u0 + R10*u1 + R20*u2;
        float y1 = R01*u0 + R11*u1 + R21*u2;
        float y2 = R02*u0 + R12*u1 + R22*u2;
        size_t o = (size_t)token * INNER + h * DH + nt * 8 + grp * 4;
        uint32_t h01 = pack_bf16(y0, y1), h23 = pack_bf16(y2, v3);
        float l0 = y0 - __uint_as_float(h01 << 16);
        float l1f = y1 - __uint_as_float(h01 & 0xFFFF0000u);
        float l2f = y2 - __uint_as_float(h23 << 16);
        float l3 = v3 - __uint_as_float(h23 & 0xFFFF0000u);
        uint2 hv; hv.x = h01; hv.y = h23;
        uint2 lv; lv.x = pack_bf16(l0, l1f); lv.y = pack_bf16(l2f, l3);
        *(uint2*)(g_atth + o) = hv;
        *(uint2*)(g_attl + o) = lv;
    }
    #undef LOAD_KV
}

// ---------------------------------------------------------------------------
extern "C" void kernel_launch(void* const* d_in, const int* in_sizes, int n_in,
                              void* d_out, int out_size)
{
    const float* x     = (const float*)d_in[0];
    const float* rot   = (const float*)d_in[1];
    const float* tr    = (const float*)d_in[2];
    const float* w_qkv = (const float*)d_in[3];
    const float* b_qkv = (const float*)d_in[4];
    const float* w_out = (const float*)d_in[5];
    const float* b_out = (const float*)d_in[6];
    float* out = (float*)d_out;

    __nv_bfloat16 *wqT_h, *wqT_l, *woT_h, *woT_l, *xh, *xl, *ath, *atl;
    cudaGetSymbolAddress((void**)&wqT_h, g_wqkvT_h);
    cudaGetSymbolAddress((void**)&wqT_l, g_wqkvT_l);
    cudaGetSymbolAddress((void**)&woT_h, g_woutT_h);
    cudaGetSymbolAddress((void**)&woT_l, g_woutT_l);
    cudaGetSymbolAddress((void**)&xh, g_xh);
    cudaGetSymbolAddress((void**)&xl, g_xl);
    cudaGetSymbolAddress((void**)&ath, g_atth);
    cudaGetSymbolAddress((void**)&atl, g_attl);

    // pre-splits (independent, run back-to-back)
    split_kernel<<<NTOK*DIMM/1024, 256>>>(x, xh, xl);
    transpose_split_kernel<<<dim3(48, 16), dim3(32, 8)>>>(w_qkv, wqT_h, wqT_l, 512, 1536);
    transpose_split_kernel<<<dim3(16, 16), dim3(32, 8)>>>(w_out, woT_h, woT_l, 512, 512);

    int mma_smem = 2 * 65536 + 128;
    cudaFuncSetAttribute(mma_gemm_kernel, cudaFuncAttributeMaxDynamicSharedMemorySize, mma_smem);

    // qkv: M=8192, Ntot=1536 -> split bf16 q/k/v
    mma_gemm_kernel<<<dim3(12, 64), 256, mma_smem>>>(xh, xl, wqT_h, wqT_l, b_qkv, rot, tr, nullptr, 0);

    // attention (mma.sync bf16-split flash, fused softmax/PV)
    int attn_smem = 2 * ABUF + 32768 + 128;
    cudaFuncSetAttribute(attn_kernel, cudaFuncAttributeMaxDynamicSharedMemorySize, attn_smem);
    attn_kernel<<<dim3(8, 64), 256, attn_smem>>>(rot, tr);

    // out projection: M=8192, Ntot=512
    mma_gemm_kernel<<<dim3(4, 64), 256, mma_smem>>>(ath, atl, woT_h, woT_l, b_out, nullptr, nullptr, out, 1);
}

// round 7
// speedup vs baseline: 3.6236x; 1.0298x over previous
#include <cuda_runtime.h>
#include <cuda_bf16.h>
#include <cstdint>
#include <math.h>

#define BB 8
#define NN 1024
#define DIMM 512
#define HH 8
#define DH 64
#define NTOK (BB*NN)          // 8192
#define INNER (HH*DH)         // 512

// Scratch (allocation-free rule: __device__ globals)
__device__ __nv_bfloat16 g_xh[(size_t)NTOK*DIMM];
__device__ __nv_bfloat16 g_xl[(size_t)NTOK*DIMM];
__device__ __nv_bfloat16 g_atth[(size_t)NTOK*INNER];
__device__ __nv_bfloat16 g_attl[(size_t)NTOK*INNER];
__device__ __nv_bfloat16 g_wqkvT_h[3*INNER*DIMM];
__device__ __nv_bfloat16 g_wqkvT_l[3*INNER*DIMM];
__device__ __nv_bfloat16 g_woutT_h[DIMM*INNER];
__device__ __nv_bfloat16 g_woutT_l[DIMM*INNER];
// pre-split bf16 q/k/v, head-major [bh][n][64]; q pre-scaled by DH^-0.5 * log2(e)
__device__ __nv_bfloat16 g_qh[BB*HH*NN*DH];
__device__ __nv_bfloat16 g_ql[BB*HH*NN*DH];
__device__ __nv_bfloat16 g_kh[BB*HH*NN*DH];
__device__ __nv_bfloat16 g_kl[BB*HH*NN*DH];
__device__ __nv_bfloat16 g_vh[BB*HH*NN*DH];
__device__ __nv_bfloat16 g_vl[BB*HH*NN*DH];

// ===================== helpers =====================
__device__ __forceinline__ uint32_t smem_to_u32(const void* p) {
    uint32_t a;
    asm("{ .reg .u64 t; cvta.to.shared.u64 t, %1; cvt.u32.u64 %0, t; }"
        : "=r"(a) : "l"(p));
    return a;
}
#define SW128(o) ((o) ^ (((o) >> 3) & 0x70))
#define SW64(o)  ((o) ^ (((o) >> 3) & 0x30))

__device__ __forceinline__ void ldmx4(uint32_t* r, uint32_t a) {
    asm volatile("ldmatrix.sync.aligned.m8n8.x4.shared.b16 {%0,%1,%2,%3}, [%4];"
        : "=r"(r[0]), "=r"(r[1]), "=r"(r[2]), "=r"(r[3]) : "r"(a));
}
__device__ __forceinline__ void ldmx4t(uint32_t* r, uint32_t a) {
    asm volatile("ldmatrix.sync.aligned.m8n8.x4.trans.shared.b16 {%0,%1,%2,%3}, [%4];"
        : "=r"(r[0]), "=r"(r[1]), "=r"(r[2]), "=r"(r[3]) : "r"(a));
}
__device__ __forceinline__ void mma16816(float* d, const uint32_t* a, const uint32_t* b) {
    asm volatile("mma.sync.aligned.m16n8k16.row.col.f32.bf16.bf16.f32 "
        "{%0,%1,%2,%3}, {%4,%5,%6,%7}, {%8,%9}, {%0,%1,%2,%3};"
        : "+f"(d[0]), "+f"(d[1]), "+f"(d[2]), "+f"(d[3])
        : "r"(a[0]), "r"(a[1]), "r"(a[2]), "r"(a[3]), "r"(b[0]), "r"(b[1]));
}
__device__ __forceinline__ void cp16(uint32_t dst, const void* src) {
    asm volatile("cp.async.cg.shared.global [%0], [%1], 16;" :: "r"(dst), "l"(src));
}
#define CP_COMMIT() asm volatile("cp.async.commit_group;" ::: "memory")
#define CP_WAIT(n)  asm volatile("cp.async.wait_group %0;" :: "n"(n) : "memory")

__device__ __forceinline__ uint32_t pack_bf16(float lo, float hi) {
    uint32_t r;
    asm("cvt.rn.bf16x2.f32 %0, %1, %2;" : "=r"(r) : "f"(hi), "f"(lo));
    return r;
}
__device__ __forceinline__ float ex2f(float x) {
    float r; asm("ex2.approx.f32 %0, %1;" : "=f"(r) : "f"(x)); return r;
}

// ===================== elementwise fp32 -> split bf16 =====================
__global__ void split_kernel(const float* __restrict__ src,
                             __nv_bfloat16* __restrict__ dh,
                             __nv_bfloat16* __restrict__ dl)
{
    int i = blockIdx.x * 256 + threadIdx.x;
    float4 f = ((const float4*)src)[i];
    uint32_t h01 = pack_bf16(f.x, f.y), h23 = pack_bf16(f.z, f.w);
    float l0 = f.x - __uint_as_float(h01 << 16);
    float l1 = f.y - __uint_as_float(h01 & 0xFFFF0000u);
    float l2 = f.z - __uint_as_float(h23 << 16);
    float l3 = f.w - __uint_as_float(h23 & 0xFFFF0000u);
    uint2 hv; hv.x = h01; hv.y = h23;
    uint2 lv; lv.x = pack_bf16(l0, l1); lv.y = pack_bf16(l2, l3);
    ((uint2*)dh)[i] = hv;
    ((uint2*)dl)[i] = lv;
}

// ===================== transpose + bf16-split of W =====================
__global__ void transpose_split_kernel(const float* __restrict__ src,
                                       __nv_bfloat16* __restrict__ dh,
                                       __nv_bfloat16* __restrict__ dl,
                                       int K, int N)
{
    __shared__ float ts[32][33];
    int n0 = blockIdx.x << 5, k0 = blockIdx.y << 5;
    int tx = threadIdx.x, ty = threadIdx.y;
    #pragma unroll
    for (int i = 0; i < 32; i += 8)
        ts[ty + i][tx] = src[(size_t)(k0 + ty + i) * N + n0 + tx];
    __syncthreads();
    #pragma unroll
    for (int i = 0; i < 32; i += 8) {
        float v = ts[tx][ty + i];
        __nv_bfloat16 h = __float2bfloat16(v);
        float lo = v - __bfloat162float(h);
        size_t o = (size_t)(n0 + ty + i) * K + k0 + tx;
        dh[o] = h;
        dl[o] = __float2bfloat16(lo);
    }
}

// ===================== mma.sync bf16-split GEMM =====================
// K-chunk 32, SW64 (64B rows), 2 buffers x 32KB -> 2 CTAs/SM.
// mode 0: qkv (pose epilogue -> split q/k/v), mode 1: out proj (bias -> outp)
__global__ __launch_bounds__(256, 2) void mma_gemm_kernel(
    const __nv_bfloat16* __restrict__ Ah,
    const __nv_bfloat16* __restrict__ Al,
    const __nv_bfloat16* __restrict__ Bh,
    const __nv_bfloat16* __restrict__ Bl,
    const float* __restrict__ bias,
    const float* __restrict__ rot, const float* __restrict__ tr,
    float* __restrict__ outp, int mode)
{
    extern __shared__ char smem[];
    uint32_t raw = smem_to_u32(smem);
    uint32_t base = (raw + 127) & ~127u;
    int t = threadIdx.x, lane = t & 31, w = t >> 5;
    int m0 = blockIdx.y << 7, n0 = blockIdx.x << 7;
    int mbase = (w >> 2) * 64, nbase = (w & 3) * 32;

    // loader: per tile (8KB = 512 x 16B chunks) each thread does 2
    int rowc[2], k16c[2]; uint32_t swc[2];
    #pragma unroll
    for (int c = 0; c < 2; c++) {
        int ci = t + c * 256;
        rowc[c] = ci >> 2; k16c[c] = ci & 3;
        swc[c] = SW64((uint32_t)(rowc[c] * 64 + k16c[c] * 16));
    }

    float acc[4][4][4] = {};

    #define LOAD_ALL(kc, bb) do { \
        uint32_t bp = base + (bb) * 32768; \
        _Pragma("unroll") \
        for (int c = 0; c < 2; c++) { \
            size_t ga = (size_t)(m0 + rowc[c]) * 512 + (kc) * 32 + k16c[c] * 8; \
            size_t gb = (size_t)(n0 + rowc[c]) * 512 + (kc) * 32 + k16c[c] * 8; \
            cp16(bp +         swc[c], Ah + ga); \
            cp16(bp +  8192 + swc[c], Al + ga); \
            cp16(bp + 16384 + swc[c], Bh + gb); \
            cp16(bp + 24576 + swc[c], Bl + gb); \
        } \
        CP_COMMIT(); \
    } while (0)

    int arow = lane & 15;
    int acolb = (lane >> 4) * 16;
    int bg = lane >> 3;
    int brow_in = lane & 7;

    LOAD_ALL(0, 0);
    CP_WAIT(0);
    __syncthreads();

    int buf = 0;
    for (int kc = 0; kc < 16; kc++) {
        if (kc < 15) LOAD_ALL(kc + 1, buf ^ 1);
        uint32_t AhS = base + buf * 32768;
        uint32_t AlS = AhS + 8192;
        uint32_t BhS = AhS + 16384;
        uint32_t BlS = AhS + 24576;
        #pragma unroll
        for (int ks = 0; ks < 2; ks++) {
            uint32_t ah[4][4], al[4][4], bhf[4][2], blf[4][2];
            #pragma unroll
            for (int i = 0; i < 4; i++) {
                uint32_t off = SW64((uint32_t)((mbase + i*16 + arow) * 64 + ks*32 + acolb));
                ldmx4(ah[i], AhS + off);
                ldmx4(al[i], AlS + off);
            }
            #pragma unroll
            for (int jp = 0; jp < 2; jp++) {
                uint32_t off = SW64((uint32_t)((nbase + jp*16 + ((bg >> 1) << 3) + brow_in) * 64
                                               + ks*32 + ((bg & 1) << 4)));
                uint32_t r[4];
                ldmx4(r, BhS + off);
                bhf[jp*2][0] = r[0]; bhf[jp*2][1] = r[1];
                bhf[jp*2+1][0] = r[2]; bhf[jp*2+1][1] = r[3];
                ldmx4(r, BlS + off);
                blf[jp*2][0] = r[0]; blf[jp*2][1] = r[1];
                blf[jp*2+1][0] = r[2]; blf[jp*2+1][1] = r[3];
            }
            #pragma unroll
            for (int i = 0; i < 4; i++)
                #pragma unroll
                for (int j = 0; j < 4; j++) {
                    mma16816(acc[i][j], ah[i], bhf[j]);
                    mma16816(acc[i][j], ah[i], blf[j]);
                    mma16816(acc[i][j], al[i], bhf[j]);
                }
        }
        if (kc < 15) CP_WAIT(0);
        __syncthreads();
        buf ^= 1;
    }

    const float QSCALE = 0.125f * 1.44269504088896f;   // DH^-0.5 * log2(e)
    bool evenlane = (lane & 1) == 0;
    #pragma unroll
    for (int i = 0; i < 4; i++) {
        int row_local = mbase + i*16 + (lane >> 2) + ((lane & 1) ? 8 : 0);
        int token = m0 + row_local;
        float R00=0,R01=0,R02=0,R10=0,R11=0,R12=0,R20=0,R21=0,R22=0,T0=0,T1=0,T2=0;
        int which = 0, b = 0, n = 0;
        if (mode == 0) {
            const float* R = rot + (size_t)token * 9;
            const float* T = tr + (size_t)token * 3;
            R00=R[0];R01=R[1];R02=R[2];R10=R[3];R11=R[4];R12=R[5];R20=R[6];R21=R[7];R22=R[8];
            T0=T[0];T1=T[1];T2=T[2];
            which = n0 >> 9;
            b = token >> 10; n = token & (NN - 1);
        }
        #pragma unroll
        for (int j = 0; j < 4; j++) {
            float x0 = __shfl_xor_sync(0xffffffffu, acc[i][j][0], 1);
            float x1 = __shfl_xor_sync(0xffffffffu, acc[i][j][1], 1);
            float x2 = __shfl_xor_sync(0xffffffffu, acc[i][j][2], 1);
            float x3 = __shfl_xor_sync(0xffffffffu, acc[i][j][3], 1);
            float v0, v1, v2, v3;
            if (evenlane) { v0 = acc[i][j][0]; v1 = acc[i][j][1]; v2 = x0; v3 = x1; }
            else          { v0 = x2; v1 = x3; v2 = acc[i][j][2]; v3 = acc[i][j][3]; }
            int cg = nbase + j*8 + ((lane >> 1) & 1) * 4;
            int cgl = n0 + cg;
            v0 += bias[cgl+0]; v1 += bias[cgl+1]; v2 += bias[cgl+2]; v3 += bias[cgl+3];
            if (mode == 0) {
                int hh2 = (cgl & 511) >> 6;
                int d = cgl & 63;
                float y0 = R00*v0 + R01*v1 + R02*v2;
                float y1 = R10*v0 + R11*v1 + R12*v2;
                float y2 = R20*v0 + R21*v1 + R22*v2;
                float y3;
                if (which == 0) {
                    y3 = v3 - (T0*y0 + T1*y1 + T2*y2);
                    y0 *= QSCALE; y1 *= QSCALE; y2 *= QSCALE; y3 *= QSCALE;
                } else {
                    y0 += T0 * v3; y1 += T1 * v3; y2 += T2 * v3;
                    y3 = v3;
                }
                __nv_bfloat16* bufh = (which == 0) ? g_qh : (which == 1 ? g_kh : g_vh);
                __nv_bfloat16* bufl = (which == 0) ? g_ql : (which == 1 ? g_kl : g_vl);
                size_t o = ((size_t)(b * HH + hh2) * NN + n) * DH + d;
                uint32_t h01 = pack_bf16(y0, y1), h23 = pack_bf16(y2, y3);
                float l0 = y0 - __uint_as_float(h01 << 16);
                float l1 = y1 - __uint_as_float(h01 & 0xFFFF0000u);
                float l2 = y2 - __uint_as_float(h23 << 16);
                float l3 = y3 - __uint_as_float(h23 & 0xFFFF0000u);
                uint2 hv; hv.x = h01; hv.y = h23;
                uint2 lv; lv.x = pack_bf16(l0, l1); lv.y = pack_bf16(l2, l3);
                *(uint2*)(bufh + o) = hv;
                *(uint2*)(bufl + o) = lv;
            } else {
                float4 ov; ov.x=v0; ov.y=v1; ov.z=v2; ov.w=v3;
                *(float4*)(outp + (size_t)token * 512 + cgl) = ov;
            }
        }
    }
    #undef LOAD_ALL
}

// ===================== mma.sync flash attention =====================
// 128 q/CTA, 8 warps x 16 q, key chunks of 64, double-buffered; 2 CTAs/SM.
// smem: buf{0,1} 32KB each: KH 8K|KL 8K|VH 8K|VL 8K ; then QH 16K | QL 16K.
#define ABUF 32768
#define AQH 65536
#define AQL 81920

__global__ __launch_bounds__(256, 2) void attn_kernel(
    const float* __restrict__ rot, const float* __restrict__ tr)
{
    extern __shared__ char smem[];
    uint32_t base = (smem_to_u32(smem) + 127) & ~127u;
    int t = threadIdx.x, lane = t & 31, w = t >> 5;
    int bh = blockIdx.y;
    int q0 = blockIdx.x << 7;
    int wm = w << 4;

    // KV loader: 2 x 16B per thread per 8KB tile
    int rkv[2], kkv[2]; uint32_t swkv[2];
    #pragma unroll
    for (int c = 0; c < 2; c++) {
        int ci = t + c * 256;
        rkv[c] = ci >> 3; kkv[c] = ci & 7;
        swkv[c] = SW128((uint32_t)(rkv[c] * 128 + kkv[c] * 16));
    }
    // Q loader: 4 x 16B per thread per 16KB tile
    int rq[4], kq[4]; uint32_t swq[4];
    #pragma unroll
    for (int c = 0; c < 4; c++) {
        int ci = t + c * 256;
        rq[c] = ci >> 3; kq[c] = ci & 7;
        swq[c] = SW128((uint32_t)(rq[c] * 128 + kq[c] * 16));
    }
    const size_t bhbase = (size_t)bh * NN * DH;

    #define LOAD_KV(cc, bb) do { \
        uint32_t bp = base + (bb) * ABUF; \
        _Pragma("unroll") \
        for (int c = 0; c < 2; c++) { \
            size_t go = bhbase + ((size_t)((cc) * 64 + rkv[c])) * 64 + kkv[c] * 8; \
            cp16(bp +         swkv[c], g_kh + go); \
            cp16(bp +  8192 + swkv[c], g_kl + go); \
            cp16(bp + 16384 + swkv[c], g_vh + go); \
            cp16(bp + 24576 + swkv[c], g_vl + go); \
        } \
        CP_COMMIT(); \
    } while (0)

    {
        #pragma unroll
        for (int c = 0; c < 4; c++) {
            size_t go = bhbase + ((size_t)(q0 + rq[c])) * 64 + kq[c] * 8;
            cp16(base + AQH + swq[c], g_qh + go);
            cp16(base + AQL + swq[c], g_ql + go);
        }
        CP_COMMIT();
    }
    LOAD_KV(0, 0);
    CP_WAIT(1);
    __syncthreads();

    int bg = lane >> 3, brow_in = lane & 7;

    float acc[8][4] = {};
    float m1 = -1e30f, m2 = -1e30f, l1 = 0.f, l2 = 0.f;

    int buf = 0;
    for (int kc = 0; kc < 16; kc++) {
        if (kc < 15) LOAD_KV(kc + 1, buf ^ 1);
        CP_WAIT(1);
        if (kc == 15) CP_WAIT(0);
        __syncthreads();
        uint32_t KHs = base + buf * ABUF;
        uint32_t KLs = KHs + 8192;
        uint32_t VHs = KHs + 16384;
        uint32_t VLs = KHs + 24576;

        // ---- scores (log2 domain): 16 q x 64 keys ----
        float s[8][4] = {};
        #pragma unroll
        for (int ks = 0; ks < 4; ks++) {
            uint32_t qoff = SW128((uint32_t)((wm + (lane & 15)) * 128
                                             + ks*32 + (lane >> 4) * 16));
            uint32_t qh[4], ql[4];
            ldmx4(qh, base + AQH + qoff);
            ldmx4(ql, base + AQL + qoff);
            #pragma unroll
            for (int jp = 0; jp < 4; jp++) {
                uint32_t off = SW128((uint32_t)((jp*16 + ((bg >> 1) << 3) + brow_in) * 128
                                                + ks*32 + ((bg & 1) << 4)));
                uint32_t rh[4], rl[4];
                ldmx4(rh, KHs + off);
                ldmx4(rl, KLs + off);
                uint32_t bh0[2] = {rh[0], rh[1]}, bh1[2] = {rh[2], rh[3]};
                uint32_t bl0[2] = {rl[0], rl[1]}, bl1[2] = {rl[2], rl[3]};
                mma16816(s[2*jp],   qh, bh0);
                mma16816(s[2*jp],   qh, bl0);
                mma16816(s[2*jp],   ql, bh0);
                mma16816(s[2*jp+1], qh, bh1);
                mma16816(s[2*jp+1], qh, bl1);
                mma16816(s[2*jp+1], ql, bh1);
            }
        }

        // ---- max reduce ----
        float mloc1 = -1e30f, mloc2 = -1e30f;
        #pragma unroll
        for (int nt = 0; nt < 8; nt++) {
            mloc1 = fmaxf(mloc1, fmaxf(s[nt][0], s[nt][1]));
            mloc2 = fmaxf(mloc2, fmaxf(s[nt][2], s[nt][3]));
        }
        mloc1 = fmaxf(mloc1, __shfl_xor_sync(0xffffffffu, mloc1, 1));
        mloc1 = fmaxf(mloc1, __shfl_xor_sync(0xffffffffu, mloc1, 2));
        mloc2 = fmaxf(mloc2, __shfl_xor_sync(0xffffffffu, mloc2, 1));
        mloc2 = fmaxf(mloc2, __shfl_xor_sync(0xffffffffu, mloc2, 2));
        float m1n = fmaxf(m1, mloc1), m2n = fmaxf(m2, mloc2);
        float a1 = ex2f(m1 - m1n), a2 = ex2f(m2 - m2n);
        m1 = m1n; m2 = m2n;

        #pragma unroll
        for (int nt = 0; nt < 8; nt++) {
            acc[nt][0] *= a1; acc[nt][1] *= a1;
            acc[nt][2] *= a2; acc[nt][3] *= a2;
        }

        // ---- fused exp + pack + PV per 16-key slice ----
        float ps1 = 0.f, ps2 = 0.f;
        #pragma unroll
        for (int kx = 0; kx < 4; kx++) {
            float p00 = ex2f(s[2*kx][0]   - m1n);
            float p01 = ex2f(s[2*kx][1]   - m1n);
            float p02 = ex2f(s[2*kx][2]   - m2n);
            float p03 = ex2f(s[2*kx][3]   - m2n);
            float p10 = ex2f(s[2*kx+1][0] - m1n);
            float p11 = ex2f(s[2*kx+1][1] - m1n);
            float p12 = ex2f(s[2*kx+1][2] - m2n);
            float p13 = ex2f(s[2*kx+1][3] - m2n);
            ps1 += p00 + p01 + p10 + p11;
            ps2 += p02 + p03 + p12 + p13;
            uint32_t ph[4], pl[4], h;
            h = pack_bf16(p00, p01); ph[0] = h;
            pl[0] = pack_bf16(p00 - __uint_as_float(h << 16),
                              p01 - __uint_as_float(h & 0xFFFF0000u));
            h = pack_bf16(p02, p03); ph[1] = h;
            pl[1] = pack_bf16(p02 - __uint_as_float(h << 16),
                              p03 - __uint_as_float(h & 0xFFFF0000u));
            h = pack_bf16(p10, p11); ph[2] = h;
            pl[2] = pack_bf16(p10 - __uint_as_float(h << 16),
                              p11 - __uint_as_float(h & 0xFFFF0000u));
            h = pack_bf16(p12, p13); ph[3] = h;
            pl[3] = pack_bf16(p12 - __uint_as_float(h << 16),
                              p13 - __uint_as_float(h & 0xFFFF0000u));
            #pragma unroll
            for (int np = 0; np < 4; np++) {
                uint32_t off = SW128((uint32_t)((kx*16 + (lane & 15)) * 128
                                                + np*32 + (lane >> 4) * 16));
                uint32_t rh[4], rl[4];
                ldmx4t(rh, VHs + off);
                ldmx4t(rl, VLs + off);
                uint32_t vh0[2] = {rh[0], rh[1]}, vh1[2] = {rh[2], rh[3]};
                uint32_t vl0[2] = {rl[0], rl[1]}, vl1[2] = {rl[2], rl[3]};
                mma16816(acc[2*np],   ph, vh0);
                mma16816(acc[2*np],   ph, vl0);
                mma16816(acc[2*np],   pl, vh0);
                mma16816(acc[2*np+1], ph, vh1);
                mma16816(acc[2*np+1], ph, vl1);
                mma16816(acc[2*np+1], pl, vh1);
            }
        }
        ps1 += __shfl_xor_sync(0xffffffffu, ps1, 1);
        ps1 += __shfl_xor_sync(0xffffffffu, ps1, 2);
        ps2 += __shfl_xor_sync(0xffffffffu, ps2, 1);
        ps2 += __shfl_xor_sync(0xffffffffu, ps2, 2);
        l1 = l1 * a1 + ps1;
        l2 = l2 * a2 + ps2;

        __syncthreads();
        buf ^= 1;
    }

    // ---- epilogue: normalize + inverse pose + relayout -> split bf16 ----
    float inv1 = 1.f / l1, inv2 = 1.f / l2;
    bool odd = lane & 1;
    float inv = odd ? inv2 : inv1;
    int r = (lane >> 2) + (odd ? 8 : 0);
    int nq = q0 + wm + r;
    int b = bh >> 3, h = bh & 7;
    int token = b * NN + nq;
    const float* R = rot + (size_t)token * 9;
    const float* T = tr + (size_t)token * 3;
    float R00=R[0],R01=R[1],R02=R[2],R10=R[3],R11=R[4],R12=R[5],R20=R[6],R21=R[7],R22=R[8];
    float T0=T[0],T1=T[1],T2=T[2];
    int grp = (lane >> 1) & 1;
    #pragma unroll
    for (int nt = 0; nt < 8; nt++) {
        float o0 = acc[nt][0], o1 = acc[nt][1], o2 = acc[nt][2], o3 = acc[nt][3];
        float x0 = __shfl_xor_sync(0xffffffffu, o0, 1);
        float x1 = __shfl_xor_sync(0xffffffffu, o1, 1);
        float x2 = __shfl_xor_sync(0xffffffffu, o2, 1);
        float x3 = __shfl_xor_sync(0xffffffffu, o3, 1);
        float v0, v1, v2, v3;
        if (!odd) { v0 = o0; v1 = o1; v2 = x0; v3 = x1; }
        else      { v0 = x2; v1 = x3; v2 = o2; v3 = o3; }
        v0 *= inv; v1 *= inv; v2 *= inv; v3 *= inv;
        float u0 = v0 - T0*v3, u1 = v1 - T1*v3, u2 = v2 - T2*v3;
        float y0 = R00*u0 + R10*u1 + R20*u2;
        float y1 = R01*u0 + R11*u1 + R21*u2;
        float y2 = R02*u0 + R12*u1 + R22*u2;
        size_t o = (size_t)token * INNER + h * DH + nt * 8 + grp * 4;
        uint32_t h01 = pack_bf16(y0, y1), h23 = pack_bf16(y2, v3);
        float l0 = y0 - __uint_as_float(h01 << 16);
        float l1f = y1 - __uint_as_float(h01 & 0xFFFF0000u);
        float l2f = y2 - __uint_as_float(h23 << 16);
        float l3 = v3 - __uint_as_float(h23 & 0xFFFF0000u);
        uint2 hv; hv.x = h01; hv.y = h23;
        uint2 lv; lv.x = pack_bf16(l0, l1f); lv.y = pack_bf16(l2f, l3);
        *(uint2*)(g_atth + o) = hv;
        *(uint2*)(g_attl + o) = lv;
    }
    #undef LOAD_KV
}

// ---------------------------------------------------------------------------
extern "C" void kernel_launch(void* const* d_in, const int* in_sizes, int n_in,
                              void* d_out, int out_size)
{
    const float* x     = (const float*)d_in[0];
    const float* rot   = (const float*)d_in[1];
    const float* tr    = (const float*)d_in[2];
    const float* w_qkv = (const float*)d_in[3];
    const float* b_qkv = (const float*)d_in[4];
    const float* w_out = (const float*)d_in[5];
    const float* b_out = (const float*)d_in[6];
    float* out = (float*)d_out;

    __nv_bfloat16 *wqT_h, *wqT_l, *woT_h, *woT_l, *xh, *xl, *ath, *atl;
    cudaGetSymbolAddress((void**)&wqT_h, g_wqkvT_h);
    cudaGetSymbolAddress((void**)&wqT_l, g_wqkvT_l);
    cudaGetSymbolAddress((void**)&woT_h, g_woutT_h);
    cudaGetSymbolAddress((void**)&woT_l, g_woutT_l);
    cudaGetSymbolAddress((void**)&xh, g_xh);
    cudaGetSymbolAddress((void**)&xl, g_xl);
    cudaGetSymbolAddress((void**)&ath, g_atth);
    cudaGetSymbolAddress((void**)&atl, g_attl);

    split_kernel<<<NTOK*DIMM/1024, 256>>>(x, xh, xl);
    transpose_split_kernel<<<dim3(48, 16), dim3(32, 8)>>>(w_qkv, wqT_h, wqT_l, 512, 1536);
    transpose_split_kernel<<<dim3(16, 16), dim3(32, 8)>>>(w_out, woT_h, woT_l, 512, 512);

    int mma_smem = 2 * 32768 + 128;    // 64KB + pad -> 2 CTAs/SM
    cudaFuncSetAttribute(mma_gemm_kernel, cudaFuncAttributeMaxDynamicSharedMemorySize, mma_smem);

    // qkv: M=8192, Ntot=1536 -> split bf16 q/k/v
    mma_gemm_kernel<<<dim3(12, 64), 256, mma_smem>>>(xh, xl, wqT_h, wqT_l, b_qkv, rot, tr, nullptr, 0);

    // attention (mma.sync bf16-split flash, 64-key chunks, 2 CTAs/SM)
    int attn_smem = 2 * ABUF + 32768 + 128;   // 96KB + pad
    cudaFuncSetAttribute(attn_kernel, cudaFuncAttributeMaxDynamicSharedMemorySize, attn_smem);
    attn_kernel<<<dim3(8, 64), 256, attn_smem>>>(rot, tr);

    // out projection: M=8192, Ntot=512
    mma_gemm_kernel<<<dim3(4, 64), 256, mma_smem>>>(ath, atl, woT_h, woT_l, b_out, nullptr, nullptr, out, 1);
}